// round 1
// baseline (speedup 1.0000x reference)
#include <cuda_runtime.h>
#include <math.h>

#define S_LEN 2048
#define BATCH 2
#define HEADS 16
#define DKV 64
#define DMODEL 1024
#define NPOS (2*S_LEN-1)   // 4095

// ---------------- device scratch (no allocations allowed) ----------------
__device__ float g_q[BATCH*HEADS*S_LEN*DKV];     // [B,H,S,Dk], pre-scaled by 1/8
__device__ float g_k[BATCH*HEADS*S_LEN*DKV];
__device__ float g_v[BATCH*HEADS*S_LEN*DKV];
__device__ float g_ao[BATCH*S_LEN*DMODEL];       // [B,S,H*Dk]
__device__ float g_bias[HEADS*NPOS];             // bias[h][delta+2047]

// ---------------- relative position bias table ----------------
// bucket(delta): sign*16 + (ad<8 ? ad : min(8 + floor(2*log2(ad/8)), 15))
// exact integer formula: 8 + floor(2*log2(ad/8)) = 2 + floor(log2(ad*ad))
__global__ void bias_table_kernel(const float* __restrict__ rel_bias) {
    int idx = blockIdx.x * blockDim.x + threadIdx.x;
    if (idx >= HEADS * NPOS) return;
    int h = idx / NPOS;
    int delta = (idx % NPOS) - (S_LEN - 1);
    int ad = delta < 0 ? -delta : delta;
    int bucket = (delta > 0) ? 16 : 0;
    if (ad < 8) {
        bucket += ad;
    } else {
        int lg = 31 - __clz(ad * ad);      // floor(2*log2(ad)), ad^2 < 2^22
        int bl = lg + 2;                   // 8 + (lg - 6)
        bucket += (bl > 15) ? 15 : bl;
    }
    g_bias[idx] = rel_bias[bucket * HEADS + h];
}

// ---------------- fp32 SGEMM: C[M,N] = A[M,K] @ B[K,N] ----------------
// 128x128 tile, BK=8, 256 threads, 8x8 microtile.
// permute=1: C treated as q/k/v scratch with [B,H,S,Dk] layout, scaled.
__global__ __launch_bounds__(256) void sgemm128(
    const float* __restrict__ A, const float* __restrict__ B,
    float* __restrict__ C, int M, int N, int K, float scale, int permute)
{
    __shared__ float As[8][128];
    __shared__ float Bs[8][128];
    int t  = threadIdx.x;
    int bx = blockIdx.x, by = blockIdx.y;
    int tx = t & 15, ty = t >> 4;

    float acc[8][8];
#pragma unroll
    for (int i = 0; i < 8; i++)
#pragma unroll
        for (int j = 0; j < 8; j++) acc[i][j] = 0.f;

    const float* Ab = A + (size_t)(by * 128) * K;
    const float* Bb = B + bx * 128;
    int arow = t >> 1, acol = (t & 1) * 4;
    int brow = t >> 5, bcol = (t & 31) * 4;

    for (int k0 = 0; k0 < K; k0 += 8) {
        float4 a = *(const float4*)(Ab + (size_t)arow * K + k0 + acol);
        As[acol + 0][arow] = a.x; As[acol + 1][arow] = a.y;
        As[acol + 2][arow] = a.z; As[acol + 3][arow] = a.w;
        float4 bv = *(const float4*)(Bb + (size_t)(k0 + brow) * N + bcol);
        *(float4*)&Bs[brow][bcol] = bv;
        __syncthreads();
#pragma unroll
        for (int k = 0; k < 8; k++) {
            float4 a0 = *(float4*)&As[k][ty * 8];
            float4 a1 = *(float4*)&As[k][ty * 8 + 4];
            float4 b0 = *(float4*)&Bs[k][tx * 8];
            float4 b1 = *(float4*)&Bs[k][tx * 8 + 4];
            float ra[8] = {a0.x,a0.y,a0.z,a0.w,a1.x,a1.y,a1.z,a1.w};
            float rb[8] = {b0.x,b0.y,b0.z,b0.w,b1.x,b1.y,b1.z,b1.w};
#pragma unroll
            for (int i = 0; i < 8; i++)
#pragma unroll
                for (int j = 0; j < 8; j++) acc[i][j] += ra[i] * rb[j];
        }
        __syncthreads();
    }

#pragma unroll
    for (int i = 0; i < 8; i++) {
        int m = by * 128 + ty * 8 + i;
#pragma unroll
        for (int j = 0; j < 8; j++) {
            int n = bx * 128 + tx * 8 + j;
            float v = acc[i][j] * scale;
            if (permute) {
                int b = m >> 11, s = m & 2047;
                int h = n >> 6,  d = n & 63;
                C[(((size_t)(b * HEADS + h) * S_LEN) + s) * DKV + d] = v;
            } else {
                C[(size_t)m * N + n] = v;
            }
        }
    }
}

// ---------------- flash attention ----------------
// grid: (S/64 qtiles, B*H). 256 threads, 4x4 microtile on 64x64 tiles.
__global__ __launch_bounds__(256) void attn_kernel(const int* __restrict__ mask) {
    extern __shared__ float sm[];
    float* Qs  = sm;              // 64*65
    float* Ks  = Qs + 64 * 65;
    float* Vs  = Ks + 64 * 65;
    float* Ps  = Vs + 64 * 65;
    float* bs  = Ps + 64 * 65;    // 127 (pad to 128)
    float* msk = bs + 128;        // 64

    int t  = threadIdx.x;
    int qt = blockIdx.x, bh = blockIdx.y;
    int b = bh >> 4, h = bh & 15;
    int q0 = qt * 64;

    const float* Qg  = g_q + ((size_t)bh * S_LEN + q0) * DKV;
    const float* Kg0 = g_k + (size_t)bh * S_LEN * DKV;
    const float* Vg0 = g_v + (size_t)bh * S_LEN * DKV;

    // load Q tile [64,64]
    for (int i = t; i < 64 * 16; i += 256) {
        int row = i >> 4, c4 = (i & 15) * 4;
        float4 qv = *(const float4*)(Qg + row * 64 + c4);
        float* d = &Qs[row * 65 + c4];
        d[0] = qv.x; d[1] = qv.y; d[2] = qv.z; d[3] = qv.w;
    }

    int tx = t & 15, ty = t >> 4;
    int r0 = ty * 4, c0 = tx * 4;
    float m_i[4] = {-INFINITY, -INFINITY, -INFINITY, -INFINITY};
    float l_i[4] = {0.f, 0.f, 0.f, 0.f};
    float accO[4][4];
#pragma unroll
    for (int i = 0; i < 4; i++)
#pragma unroll
        for (int j = 0; j < 4; j++) accO[i][j] = 0.f;

    for (int kt = 0; kt < S_LEN / 64; kt++) {
        int kb = kt * 64;
        for (int i = t; i < 64 * 16; i += 256) {
            int row = i >> 4, c4 = (i & 15) * 4;
            float4 kv = *(const float4*)(Kg0 + (size_t)(kb + row) * 64 + c4);
            float* dk = &Ks[row * 65 + c4];
            dk[0] = kv.x; dk[1] = kv.y; dk[2] = kv.z; dk[3] = kv.w;
            float4 vv = *(const float4*)(Vg0 + (size_t)(kb + row) * 64 + c4);
            float* dv = &Vs[row * 65 + c4];
            dv[0] = vv.x; dv[1] = vv.y; dv[2] = vv.z; dv[3] = vv.w;
        }
        if (t < 127) {
            int delta = kb - q0 - 63 + t;                 // in [-2047, 2047]
            bs[t] = g_bias[h * NPOS + delta + (S_LEN - 1)];
        }
        if (t >= 128 && t < 192) {
            int j = t - 128;
            msk[j] = mask[b * S_LEN + kb + j] ? 0.0f : -1e30f;
        }
        __syncthreads();

        // S = Q @ K^T (64x64x64)
        float s[4][4];
#pragma unroll
        for (int i = 0; i < 4; i++)
#pragma unroll
            for (int j = 0; j < 4; j++) s[i][j] = 0.f;
#pragma unroll 8
        for (int d = 0; d < 64; d++) {
            float rq[4], rk[4];
#pragma unroll
            for (int i = 0; i < 4; i++) rq[i] = Qs[(r0 + i) * 65 + d];
#pragma unroll
            for (int j = 0; j < 4; j++) rk[j] = Ks[(c0 + j) * 65 + d];
#pragma unroll
            for (int i = 0; i < 4; i++)
#pragma unroll
                for (int j = 0; j < 4; j++) s[i][j] += rq[i] * rk[j];
        }

        // bias + mask + online softmax
#pragma unroll
        for (int i = 0; i < 4; i++) {
            float tm = -INFINITY;
#pragma unroll
            for (int j = 0; j < 4; j++) {
                s[i][j] += bs[(c0 + j) - (r0 + i) + 63] + msk[c0 + j];
                tm = fmaxf(tm, s[i][j]);
            }
#pragma unroll
            for (int o = 1; o < 16; o <<= 1)
                tm = fmaxf(tm, __shfl_xor_sync(0xffffffffu, tm, o));
            float mnew = fmaxf(m_i[i], tm);
            float alpha = __expf(m_i[i] - mnew);
            float rs = 0.f;
#pragma unroll
            for (int j = 0; j < 4; j++) {
                float p = __expf(s[i][j] - mnew);
                Ps[(r0 + i) * 65 + c0 + j] = p;
                rs += p;
            }
#pragma unroll
            for (int o = 1; o < 16; o <<= 1)
                rs += __shfl_xor_sync(0xffffffffu, rs, o);
            l_i[i] = l_i[i] * alpha + rs;
            m_i[i] = mnew;
#pragma unroll
            for (int j = 0; j < 4; j++) accO[i][j] *= alpha;
        }
        __syncthreads();

        // O += P @ V (64x64x64)
#pragma unroll 8
        for (int k = 0; k < 64; k++) {
            float rp[4], rv[4];
#pragma unroll
            for (int i = 0; i < 4; i++) rp[i] = Ps[(r0 + i) * 65 + k];
#pragma unroll
            for (int j = 0; j < 4; j++) rv[j] = Vs[k * 65 + c0 + j];
#pragma unroll
            for (int i = 0; i < 4; i++)
#pragma unroll
                for (int j = 0; j < 4; j++) accO[i][j] += rp[i] * rv[j];
        }
        __syncthreads();
    }

    // write attn output [B,S,H*Dk]
#pragma unroll
    for (int i = 0; i < 4; i++) {
        float inv = 1.0f / l_i[i];
        int srow = q0 + r0 + i;
#pragma unroll
        for (int j = 0; j < 4; j++) {
            g_ao[(((size_t)b * S_LEN + srow) * HEADS + h) * DKV + c0 + j] =
                accO[i][j] * inv;
        }
    }
}

// ---------------- launch ----------------
extern "C" void kernel_launch(void* const* d_in, const int* in_sizes, int n_in,
                              void* d_out, int out_size) {
    const float* hidden   = (const float*)d_in[0];
    const int*   mask     = (const int*)  d_in[1];
    const float* Wq       = (const float*)d_in[2];
    const float* Wk       = (const float*)d_in[3];
    const float* Wv       = (const float*)d_in[4];
    const float* Wo       = (const float*)d_in[5];
    const float* rel_bias = (const float*)d_in[6];
    float* out = (float*)d_out;

    float *pq, *pk, *pv, *pao;
    cudaGetSymbolAddress((void**)&pq,  g_q);
    cudaGetSymbolAddress((void**)&pk,  g_k);
    cudaGetSymbolAddress((void**)&pv,  g_v);
    cudaGetSymbolAddress((void**)&pao, g_ao);

    // 1) bias table
    bias_table_kernel<<<(HEADS * NPOS + 255) / 256, 256>>>(rel_bias);

    // 2) QKV projections (fused permuted store, q scaled by 1/sqrt(Dk)=0.125)
    int M = BATCH * S_LEN;            // 4096
    dim3 gg(DMODEL / 128, M / 128);   // (8, 32)
    sgemm128<<<gg, 256>>>(hidden, Wq, pq, M, DMODEL, DMODEL, 0.125f, 1);
    sgemm128<<<gg, 256>>>(hidden, Wk, pk, M, DMODEL, DMODEL, 1.0f,   1);
    sgemm128<<<gg, 256>>>(hidden, Wv, pv, M, DMODEL, DMODEL, 1.0f,   1);

    // 3) flash attention
    int smem = (4 * 64 * 65 + 128 + 64) * (int)sizeof(float);  // ~67 KB
    cudaFuncSetAttribute(attn_kernel,
                         cudaFuncAttributeMaxDynamicSharedMemorySize, smem);
    attn_kernel<<<dim3(S_LEN / 64, BATCH * HEADS), 256, smem>>>(mask);

    // 4) output projection -> d_out
    sgemm128<<<gg, 256>>>(pao, Wo, out, M, DMODEL, DMODEL, 1.0f, 0);
}

// round 3
// speedup vs baseline: 1.2681x; 1.2681x over previous
#include <cuda_runtime.h>
#include <cuda_bf16.h>
#include <math.h>
#include <stdint.h>

#define S_LEN 2048
#define BATCH 2
#define HEADS 16
#define DKV 64
#define DMODEL 1024
#define NPOS (2*S_LEN-1)   // 4095
#define MTOT (BATCH*S_LEN) // 4096

// ---------------- device scratch (no allocations allowed) ----------------
__device__ float g_q[BATCH*HEADS*S_LEN*DKV];     // [B,H,S,Dk], pre-scaled by 1/8
__device__ float g_k[BATCH*HEADS*S_LEN*DKV];
__device__ float g_v[BATCH*HEADS*S_LEN*DKV];
__device__ float g_ao[BATCH*S_LEN*DMODEL];       // [B,S,H*Dk]
__device__ float g_bias[HEADS*NPOS];             // bias[h][delta+2047]

// bf16 split scratch
__device__ __nv_bfloat16 g_xh[MTOT*DMODEL];      // hidden hi
__device__ __nv_bfloat16 g_xl[MTOT*DMODEL];      // hidden lo
__device__ __nv_bfloat16 g_wh[4*DMODEL*DMODEL];  // Wq,Wk,Wv,Wo transposed [N,K] hi
__device__ __nv_bfloat16 g_wl[4*DMODEL*DMODEL];  // lo
__device__ __nv_bfloat16 g_aoh[MTOT*DMODEL];     // attn out hi
__device__ __nv_bfloat16 g_aol[MTOT*DMODEL];     // attn out lo

// ---------------- helpers ----------------
__device__ __forceinline__ uint32_t smem_u32(const void* p) {
    uint32_t a;
    asm("{ .reg .u64 t; cvta.to.shared.u64 t, %1; cvt.u32.u64 %0, t; }"
        : "=r"(a) : "l"(p));
    return a;
}
__device__ __forceinline__ void ldsm_x4(uint32_t* r, uint32_t addr) {
    asm volatile("ldmatrix.sync.aligned.m8n8.x4.shared.b16 {%0,%1,%2,%3}, [%4];"
                 : "=r"(r[0]), "=r"(r[1]), "=r"(r[2]), "=r"(r[3]) : "r"(addr));
}
__device__ __forceinline__ void mma_bf16(float* d, const uint32_t* a,
                                         const uint32_t* b) {
    asm volatile(
        "mma.sync.aligned.m16n8k16.row.col.f32.bf16.bf16.f32 "
        "{%0,%1,%2,%3}, {%4,%5,%6,%7}, {%8,%9}, {%0,%1,%2,%3};"
        : "+f"(d[0]), "+f"(d[1]), "+f"(d[2]), "+f"(d[3])
        : "r"(a[0]), "r"(a[1]), "r"(a[2]), "r"(a[3]), "r"(b[0]), "r"(b[1]));
}

// ---------------- relative position bias table ----------------
__global__ void bias_table_kernel(const float* __restrict__ rel_bias) {
    int idx = blockIdx.x * blockDim.x + threadIdx.x;
    if (idx >= HEADS * NPOS) return;
    int h = idx / NPOS;
    int delta = (idx % NPOS) - (S_LEN - 1);
    int ad = delta < 0 ? -delta : delta;
    int bucket = (delta > 0) ? 16 : 0;
    if (ad < 8) {
        bucket += ad;
    } else {
        int lg = 31 - __clz(ad * ad);      // floor(2*log2(ad))
        int bl = lg + 2;
        bucket += (bl > 15) ? 15 : bl;
    }
    g_bias[idx] = rel_bias[bucket * HEADS + h];
}

// ---------------- fp32 -> bf16 hi/lo split ----------------
__global__ void split_hl_kernel(const float* __restrict__ x,
                                __nv_bfloat16* __restrict__ hi,
                                __nv_bfloat16* __restrict__ lo, int n) {
    int i = (blockIdx.x * blockDim.x + threadIdx.x) * 4;
    if (i >= n) return;
    float4 v = *(const float4*)(x + i);
    __nv_bfloat16 h0 = __float2bfloat16(v.x);
    __nv_bfloat16 h1 = __float2bfloat16(v.y);
    __nv_bfloat16 h2 = __float2bfloat16(v.z);
    __nv_bfloat16 h3 = __float2bfloat16(v.w);
    __nv_bfloat16 l0 = __float2bfloat16(v.x - __bfloat162float(h0));
    __nv_bfloat16 l1 = __float2bfloat16(v.y - __bfloat162float(h1));
    __nv_bfloat16 l2 = __float2bfloat16(v.z - __bfloat162float(h2));
    __nv_bfloat16 l3 = __float2bfloat16(v.w - __bfloat162float(h3));
    __nv_bfloat162* hp = (__nv_bfloat162*)(hi + i);
    __nv_bfloat162* lp = (__nv_bfloat162*)(lo + i);
    hp[0] = __halves2bfloat162(h0, h1); hp[1] = __halves2bfloat162(h2, h3);
    lp[0] = __halves2bfloat162(l0, l1); lp[1] = __halves2bfloat162(l2, l3);
}

// ---------------- transpose + split W[K,N] -> T[N,K] hi/lo ----------------
__global__ void transpose_split_kernel(const float* __restrict__ W,
                                       __nv_bfloat16* __restrict__ Th,
                                       __nv_bfloat16* __restrict__ Tl) {
    __shared__ float tile[32][33];
    int n0 = blockIdx.x * 32, k0 = blockIdx.y * 32;
    int tx = threadIdx.x, ty = threadIdx.y;
    for (int r = ty; r < 32; r += 8)
        tile[r][tx] = W[(size_t)(k0 + r) * DMODEL + n0 + tx];
    __syncthreads();
    for (int r = ty; r < 32; r += 8) {
        float v = tile[tx][r];     // = W[k0+tx][n0+r]
        __nv_bfloat16 h = __float2bfloat16(v);
        __nv_bfloat16 l = __float2bfloat16(v - __bfloat162float(h));
        size_t o = (size_t)(n0 + r) * DMODEL + k0 + tx;
        Th[o] = h; Tl[o] = l;
    }
}

// ---------------- HMMA bf16x3 GEMM ----------------
// C[4096,1024] = A[4096,1024] @ B^T  (B stored [N,K] K-major)
// CTA 128x128 tile, BK=64, 8 warps (4m x 2n), warp tile 32x64.
#define SSTR 72   // smem row stride in bf16 (64 + 8 pad)
__global__ __launch_bounds__(256, 1) void hmma_gemm(
    const __nv_bfloat16* __restrict__ Ah, const __nv_bfloat16* __restrict__ Al,
    const __nv_bfloat16* __restrict__ Bh, const __nv_bfloat16* __restrict__ Bl,
    float* __restrict__ C, float scale, int permute)
{
    extern __shared__ __nv_bfloat16 sm16[];
    __nv_bfloat16* sAh = sm16;
    __nv_bfloat16* sAl = sAh + 128 * SSTR;
    __nv_bfloat16* sBh = sAl + 128 * SSTR;
    __nv_bfloat16* sBl = sBh + 128 * SSTR;

    const int t = threadIdx.x, wid = t >> 5, lane = t & 31;
    const int m0 = blockIdx.y * 128, n0 = blockIdx.x * 128;
    const int wm0 = (wid & 3) * 32;        // warp m offset within tile
    const int wn0 = (wid >> 2) * 64;       // warp n offset within tile

    const uint32_t uAh = smem_u32(sAh), uAl = smem_u32(sAl);
    const uint32_t uBh = smem_u32(sBh), uBl = smem_u32(sBl);

    float acc[2][8][4];
#pragma unroll
    for (int mi = 0; mi < 2; mi++)
#pragma unroll
        for (int ni = 0; ni < 8; ni++)
#pragma unroll
            for (int j = 0; j < 4; j++) acc[mi][ni][j] = 0.f;

    const int lrow = lane & 15, lkh = lane >> 4;   // ldmatrix address pattern

    for (int c = 0; c < 16; c++) {
        int k0 = c * 64;
        // stage 4 tiles [128 rows x 64 bf16]
        for (int i = t; i < 1024; i += 256) {
            int row = i >> 3, cv = i & 7;
            uint32_t so = (uint32_t)(row * SSTR + cv * 8);
            size_t ga = (size_t)(m0 + row) * DMODEL + k0 + cv * 8;
            size_t gb = (size_t)(n0 + row) * DMODEL + k0 + cv * 8;
            *(uint4*)(sAh + so) = *(const uint4*)(Ah + ga);
            *(uint4*)(sAl + so) = *(const uint4*)(Al + ga);
            *(uint4*)(sBh + so) = *(const uint4*)(Bh + gb);
            *(uint4*)(sBl + so) = *(const uint4*)(Bl + gb);
        }
        __syncthreads();

#pragma unroll
        for (int pass = 0; pass < 3; pass++) {
            uint32_t uA = (pass == 2) ? uAl : uAh;
            uint32_t uB = (pass == 1) ? uBl : uBh;
#pragma unroll
            for (int ks = 0; ks < 4; ks++) {
                int kk = ks * 16;
                uint32_t a[2][4];
#pragma unroll
                for (int mi = 0; mi < 2; mi++)
                    ldsm_x4(a[mi], uA + 2u * (uint32_t)(
                        (wm0 + mi * 16 + lrow) * SSTR + kk + lkh * 8));
                uint32_t bfr[4][4];
#pragma unroll
                for (int nt = 0; nt < 4; nt++)
                    ldsm_x4(bfr[nt], uB + 2u * (uint32_t)(
                        (wn0 + nt * 16 + lrow) * SSTR + kk + lkh * 8));
#pragma unroll
                for (int mi = 0; mi < 2; mi++)
#pragma unroll
                    for (int nt = 0; nt < 4; nt++) {
                        uint32_t b0[2] = {bfr[nt][0], bfr[nt][2]};
                        uint32_t b1[2] = {bfr[nt][1], bfr[nt][3]};
                        mma_bf16(acc[mi][nt * 2 + 0], a[mi], b0);
                        mma_bf16(acc[mi][nt * 2 + 1], a[mi], b1);
                    }
            }
        }
        __syncthreads();
    }

    // epilogue
    const int lr = lane >> 2, lc = (lane & 3) * 2;
#pragma unroll
    for (int mi = 0; mi < 2; mi++) {
#pragma unroll
        for (int half = 0; half < 2; half++) {
            int m = m0 + wm0 + mi * 16 + lr + half * 8;
#pragma unroll
            for (int ni = 0; ni < 8; ni++) {
                int n = n0 + wn0 + ni * 8 + lc;
                float2 v;
                v.x = acc[mi][ni][half * 2 + 0] * scale;
                v.y = acc[mi][ni][half * 2 + 1] * scale;
                if (permute) {
                    int b = m >> 11, s = m & 2047;
                    int h = n >> 6, d0 = n & 63;
                    *(float2*)(C + (((size_t)(b * HEADS + h) * S_LEN) + s) * DKV + d0) = v;
                } else {
                    *(float2*)(C + (size_t)m * DMODEL + n) = v;
                }
            }
        }
    }
}

// ---------------- flash attention (unchanged, verified) ----------------
__global__ __launch_bounds__(256) void attn_kernel(const int* __restrict__ mask) {
    extern __shared__ float sm[];
    float* Qs  = sm;              // 64*65
    float* Ks  = Qs + 64 * 65;
    float* Vs  = Ks + 64 * 65;
    float* Ps  = Vs + 64 * 65;
    float* bs  = Ps + 64 * 65;    // 127 (pad to 128)
    float* msk = bs + 128;        // 64

    int t  = threadIdx.x;
    int qt = blockIdx.x, bh = blockIdx.y;
    int b = bh >> 4, h = bh & 15;
    int q0 = qt * 64;

    const float* Qg  = g_q + ((size_t)bh * S_LEN + q0) * DKV;
    const float* Kg0 = g_k + (size_t)bh * S_LEN * DKV;
    const float* Vg0 = g_v + (size_t)bh * S_LEN * DKV;

    for (int i = t; i < 64 * 16; i += 256) {
        int row = i >> 4, c4 = (i & 15) * 4;
        float4 qv = *(const float4*)(Qg + row * 64 + c4);
        float* d = &Qs[row * 65 + c4];
        d[0] = qv.x; d[1] = qv.y; d[2] = qv.z; d[3] = qv.w;
    }

    int tx = t & 15, ty = t >> 4;
    int r0 = ty * 4, c0 = tx * 4;
    float m_i[4] = {-INFINITY, -INFINITY, -INFINITY, -INFINITY};
    float l_i[4] = {0.f, 0.f, 0.f, 0.f};
    float accO[4][4];
#pragma unroll
    for (int i = 0; i < 4; i++)
#pragma unroll
        for (int j = 0; j < 4; j++) accO[i][j] = 0.f;

    for (int kt = 0; kt < S_LEN / 64; kt++) {
        int kb = kt * 64;
        for (int i = t; i < 64 * 16; i += 256) {
            int row = i >> 4, c4 = (i & 15) * 4;
            float4 kv = *(const float4*)(Kg0 + (size_t)(kb + row) * 64 + c4);
            float* dk = &Ks[row * 65 + c4];
            dk[0] = kv.x; dk[1] = kv.y; dk[2] = kv.z; dk[3] = kv.w;
            float4 vv = *(const float4*)(Vg0 + (size_t)(kb + row) * 64 + c4);
            float* dv = &Vs[row * 65 + c4];
            dv[0] = vv.x; dv[1] = vv.y; dv[2] = vv.z; dv[3] = vv.w;
        }
        if (t < 127) {
            int delta = kb - q0 - 63 + t;
            bs[t] = g_bias[h * NPOS + delta + (S_LEN - 1)];
        }
        if (t >= 128 && t < 192) {
            int j = t - 128;
            msk[j] = mask[b * S_LEN + kb + j] ? 0.0f : -1e30f;
        }
        __syncthreads();

        float s[4][4];
#pragma unroll
        for (int i = 0; i < 4; i++)
#pragma unroll
            for (int j = 0; j < 4; j++) s[i][j] = 0.f;
#pragma unroll 8
        for (int d = 0; d < 64; d++) {
            float rq[4], rk[4];
#pragma unroll
            for (int i = 0; i < 4; i++) rq[i] = Qs[(r0 + i) * 65 + d];
#pragma unroll
            for (int j = 0; j < 4; j++) rk[j] = Ks[(c0 + j) * 65 + d];
#pragma unroll
            for (int i = 0; i < 4; i++)
#pragma unroll
                for (int j = 0; j < 4; j++) s[i][j] += rq[i] * rk[j];
        }

#pragma unroll
        for (int i = 0; i < 4; i++) {
            float tm = -INFINITY;
#pragma unroll
            for (int j = 0; j < 4; j++) {
                s[i][j] += bs[(c0 + j) - (r0 + i) + 63] + msk[c0 + j];
                tm = fmaxf(tm, s[i][j]);
            }
#pragma unroll
            for (int o = 1; o < 16; o <<= 1)
                tm = fmaxf(tm, __shfl_xor_sync(0xffffffffu, tm, o));
            float mnew = fmaxf(m_i[i], tm);
            float alpha = __expf(m_i[i] - mnew);
            float rs = 0.f;
#pragma unroll
            for (int j = 0; j < 4; j++) {
                float p = __expf(s[i][j] - mnew);
                Ps[(r0 + i) * 65 + c0 + j] = p;
                rs += p;
            }
#pragma unroll
            for (int o = 1; o < 16; o <<= 1)
                rs += __shfl_xor_sync(0xffffffffu, rs, o);
            l_i[i] = l_i[i] * alpha + rs;
            m_i[i] = mnew;
#pragma unroll
            for (int j = 0; j < 4; j++) accO[i][j] *= alpha;
        }
        __syncthreads();

#pragma unroll 8
        for (int k = 0; k < 64; k++) {
            float rp[4], rv[4];
#pragma unroll
            for (int i = 0; i < 4; i++) rp[i] = Ps[(r0 + i) * 65 + k];
#pragma unroll
            for (int j = 0; j < 4; j++) rv[j] = Vs[k * 65 + c0 + j];
#pragma unroll
            for (int i = 0; i < 4; i++)
#pragma unroll
                for (int j = 0; j < 4; j++) accO[i][j] += rp[i] * rv[j];
        }
        __syncthreads();
    }

#pragma unroll
    for (int i = 0; i < 4; i++) {
        float inv = 1.0f / l_i[i];
        int srow = q0 + r0 + i;
#pragma unroll
        for (int j = 0; j < 4; j++) {
            g_ao[(((size_t)b * S_LEN + srow) * HEADS + h) * DKV + c0 + j] =
                accO[i][j] * inv;
        }
    }
}

// ---------------- launch ----------------
extern "C" void kernel_launch(void* const* d_in, const int* in_sizes, int n_in,
                              void* d_out, int out_size) {
    const float* hidden   = (const float*)d_in[0];
    const int*   mask     = (const int*)  d_in[1];
    const float* Wq       = (const float*)d_in[2];
    const float* Wk       = (const float*)d_in[3];
    const float* Wv       = (const float*)d_in[4];
    const float* Wo       = (const float*)d_in[5];
    const float* rel_bias = (const float*)d_in[6];
    float* out = (float*)d_out;

    float *pq, *pk, *pv, *pao;
    __nv_bfloat16 *pxh, *pxl, *pwh, *pwl, *paoh, *paol;
    cudaGetSymbolAddress((void**)&pq,   g_q);
    cudaGetSymbolAddress((void**)&pk,   g_k);
    cudaGetSymbolAddress((void**)&pv,   g_v);
    cudaGetSymbolAddress((void**)&pao,  g_ao);
    cudaGetSymbolAddress((void**)&pxh,  g_xh);
    cudaGetSymbolAddress((void**)&pxl,  g_xl);
    cudaGetSymbolAddress((void**)&pwh,  g_wh);
    cudaGetSymbolAddress((void**)&pwl,  g_wl);
    cudaGetSymbolAddress((void**)&paoh, g_aoh);
    cudaGetSymbolAddress((void**)&paol, g_aol);

    // 1) bias table
    bias_table_kernel<<<(HEADS * NPOS + 255) / 256, 256>>>(rel_bias);

    // 2) split hidden; transpose+split weights
    int nX = MTOT * DMODEL;
    split_hl_kernel<<<nX / 4 / 256, 256>>>(hidden, pxh, pxl, nX);
    dim3 tg(32, 32), tb(32, 8);
    const size_t WSZ = (size_t)DMODEL * DMODEL;
    transpose_split_kernel<<<tg, tb>>>(Wq, pwh + 0*WSZ, pwl + 0*WSZ);
    transpose_split_kernel<<<tg, tb>>>(Wk, pwh + 1*WSZ, pwl + 1*WSZ);
    transpose_split_kernel<<<tg, tb>>>(Wv, pwh + 2*WSZ, pwl + 2*WSZ);
    transpose_split_kernel<<<tg, tb>>>(Wo, pwh + 3*WSZ, pwl + 3*WSZ);

    // 3) QKV projections on HMMA (bf16x3)
    int gsmem = 4 * 128 * SSTR * (int)sizeof(__nv_bfloat16);  // 73728
    cudaFuncSetAttribute(hmma_gemm, cudaFuncAttributeMaxDynamicSharedMemorySize, gsmem);
    dim3 gg(DMODEL / 128, MTOT / 128);  // (8, 32)
    hmma_gemm<<<gg, 256, gsmem>>>(pxh, pxl, pwh + 0*WSZ, pwl + 0*WSZ, pq, 0.125f, 1);
    hmma_gemm<<<gg, 256, gsmem>>>(pxh, pxl, pwh + 1*WSZ, pwl + 1*WSZ, pk, 1.0f,   1);
    hmma_gemm<<<gg, 256, gsmem>>>(pxh, pxl, pwh + 2*WSZ, pwl + 2*WSZ, pv, 1.0f,   1);

    // 4) flash attention
    int smem = (4 * 64 * 65 + 128 + 64) * (int)sizeof(float);
    cudaFuncSetAttribute(attn_kernel,
                         cudaFuncAttributeMaxDynamicSharedMemorySize, smem);
    attn_kernel<<<dim3(S_LEN / 64, BATCH * HEADS), 256, smem>>>(mask);

    // 5) output projection on HMMA
    split_hl_kernel<<<nX / 4 / 256, 256>>>(pao, paoh, paol, nX);
    hmma_gemm<<<gg, 256, gsmem>>>(paoh, paol, pwh + 3*WSZ, pwl + 3*WSZ, out, 1.0f, 0);
}

// round 4
// speedup vs baseline: 2.1852x; 1.7233x over previous
#include <cuda_runtime.h>
#include <cuda_bf16.h>
#include <math.h>
#include <stdint.h>

#define S_LEN 2048
#define BATCH 2
#define HEADS 16
#define DKV 64
#define DMODEL 1024
#define NPOS (2*S_LEN-1)   // 4095
#define MTOT (BATCH*S_LEN) // 4096

// ---------------- device scratch (no allocations allowed) ----------------
__device__ float g_bias[HEADS*NPOS];             // bias[h][delta+2047]

// bf16 hi/lo scratch
__device__ __nv_bfloat16 g_xh[MTOT*DMODEL];      // hidden hi
__device__ __nv_bfloat16 g_xl[MTOT*DMODEL];      // hidden lo
__device__ __nv_bfloat16 g_wh[4*DMODEL*DMODEL];  // Wq,Wk,Wv,Wo transposed [N,K] hi
__device__ __nv_bfloat16 g_wl[4*DMODEL*DMODEL];  // lo
__device__ __nv_bfloat16 g_qh[BATCH*HEADS*S_LEN*DKV];  // [B,H,S,Dk], scaled 1/8
__device__ __nv_bfloat16 g_ql[BATCH*HEADS*S_LEN*DKV];
__device__ __nv_bfloat16 g_kh[BATCH*HEADS*S_LEN*DKV];  // [B,H,S,Dk]
__device__ __nv_bfloat16 g_kl[BATCH*HEADS*S_LEN*DKV];
__device__ __nv_bfloat16 g_vth[BATCH*HEADS*DKV*S_LEN]; // [B,H,Dk,S] (V^T)
__device__ __nv_bfloat16 g_vtl[BATCH*HEADS*DKV*S_LEN];
__device__ __nv_bfloat16 g_aoh[MTOT*DMODEL];     // attn out hi [B,S,H*Dk]
__device__ __nv_bfloat16 g_aol[MTOT*DMODEL];     // attn out lo

// ---------------- helpers ----------------
__device__ __forceinline__ uint32_t smem_u32(const void* p) {
    uint32_t a;
    asm("{ .reg .u64 t; cvta.to.shared.u64 t, %1; cvt.u32.u64 %0, t; }"
        : "=r"(a) : "l"(p));
    return a;
}
__device__ __forceinline__ void ldsm_x4(uint32_t* r, uint32_t addr) {
    asm volatile("ldmatrix.sync.aligned.m8n8.x4.shared.b16 {%0,%1,%2,%3}, [%4];"
                 : "=r"(r[0]), "=r"(r[1]), "=r"(r[2]), "=r"(r[3]) : "r"(addr));
}
__device__ __forceinline__ void mma_bf16(float* d, const uint32_t* a,
                                         const uint32_t* b) {
    asm volatile(
        "mma.sync.aligned.m16n8k16.row.col.f32.bf16.bf16.f32 "
        "{%0,%1,%2,%3}, {%4,%5,%6,%7}, {%8,%9}, {%0,%1,%2,%3};"
        : "+f"(d[0]), "+f"(d[1]), "+f"(d[2]), "+f"(d[3])
        : "r"(a[0]), "r"(a[1]), "r"(a[2]), "r"(a[3]), "r"(b[0]), "r"(b[1]));
}
__device__ __forceinline__ void split2(float f0, float f1,
                                       __nv_bfloat162& hp, __nv_bfloat162& lp) {
    hp = __floats2bfloat162_rn(f0, f1);
    float2 hf = __bfloat1622float2(hp);
    lp = __floats2bfloat162_rn(f0 - hf.x, f1 - hf.y);
}

// ---------------- relative position bias table ----------------
__global__ void bias_table_kernel(const float* __restrict__ rel_bias) {
    int idx = blockIdx.x * blockDim.x + threadIdx.x;
    if (idx >= HEADS * NPOS) return;
    int h = idx / NPOS;
    int delta = (idx % NPOS) - (S_LEN - 1);
    int ad = delta < 0 ? -delta : delta;
    int bucket = (delta > 0) ? 16 : 0;
    if (ad < 8) {
        bucket += ad;
    } else {
        int lg = 31 - __clz(ad * ad);      // floor(2*log2(ad))
        int bl = lg + 2;
        bucket += (bl > 15) ? 15 : bl;
    }
    g_bias[idx] = rel_bias[bucket * HEADS + h];
}

// ---------------- fp32 -> bf16 hi/lo split ----------------
__global__ void split_hl_kernel(const float* __restrict__ x,
                                __nv_bfloat16* __restrict__ hi,
                                __nv_bfloat16* __restrict__ lo, int n) {
    int i = (blockIdx.x * blockDim.x + threadIdx.x) * 4;
    if (i >= n) return;
    float4 v = *(const float4*)(x + i);
    __nv_bfloat162 h0, l0, h1, l1;
    split2(v.x, v.y, h0, l0);
    split2(v.z, v.w, h1, l1);
    __nv_bfloat162* hp = (__nv_bfloat162*)(hi + i);
    __nv_bfloat162* lp = (__nv_bfloat162*)(lo + i);
    hp[0] = h0; hp[1] = h1;
    lp[0] = l0; lp[1] = l1;
}

// ---------------- transpose + split W[K,N] -> T[N,K] hi/lo ----------------
__global__ void transpose_split_kernel(const float* __restrict__ W,
                                       __nv_bfloat16* __restrict__ Th,
                                       __nv_bfloat16* __restrict__ Tl) {
    __shared__ float tile[32][33];
    int n0 = blockIdx.x * 32, k0 = blockIdx.y * 32;
    int tx = threadIdx.x, ty = threadIdx.y;
    for (int r = ty; r < 32; r += 8)
        tile[r][tx] = W[(size_t)(k0 + r) * DMODEL + n0 + tx];
    __syncthreads();
    for (int r = ty; r < 32; r += 8) {
        float v = tile[tx][r];     // = W[k0+tx][n0+r]
        __nv_bfloat16 h = __float2bfloat16(v);
        __nv_bfloat16 l = __float2bfloat16(v - __bfloat162float(h));
        size_t o = (size_t)(n0 + r) * DMODEL + k0 + tx;
        Th[o] = h; Tl[o] = l;
    }
}

// ---------------- HMMA bf16x3 GEMM ----------------
// C[4096,1024] = A[4096,1024] @ B^T  (B stored [N,K] K-major)
// CTA 128x128 tile, BK=64, 8 warps (4m x 2n), warp tile 32x64.
// mode 0: fp32 row-major; mode 1: bf16 hi/lo [B,H,S,Dk]; mode 2: bf16 hi/lo [B,H,Dk,S]
#define SSTR 72   // smem row stride in bf16 (64 + 8 pad)
__global__ __launch_bounds__(256, 1) void hmma_gemm(
    const __nv_bfloat16* __restrict__ Ah, const __nv_bfloat16* __restrict__ Al,
    const __nv_bfloat16* __restrict__ Bh, const __nv_bfloat16* __restrict__ Bl,
    float* __restrict__ Cf, __nv_bfloat16* __restrict__ Ch,
    __nv_bfloat16* __restrict__ Cl, float scale, int mode)
{
    extern __shared__ __nv_bfloat16 sm16[];
    __nv_bfloat16* sAh = sm16;
    __nv_bfloat16* sAl = sAh + 128 * SSTR;
    __nv_bfloat16* sBh = sAl + 128 * SSTR;
    __nv_bfloat16* sBl = sBh + 128 * SSTR;

    const int t = threadIdx.x, wid = t >> 5, lane = t & 31;
    const int m0 = blockIdx.y * 128, n0 = blockIdx.x * 128;
    const int wm0 = (wid & 3) * 32;        // warp m offset within tile
    const int wn0 = (wid >> 2) * 64;       // warp n offset within tile

    const uint32_t uAh = smem_u32(sAh), uAl = smem_u32(sAl);
    const uint32_t uBh = smem_u32(sBh), uBl = smem_u32(sBl);

    float acc[2][8][4];
#pragma unroll
    for (int mi = 0; mi < 2; mi++)
#pragma unroll
        for (int ni = 0; ni < 8; ni++)
#pragma unroll
            for (int j = 0; j < 4; j++) acc[mi][ni][j] = 0.f;

    const int lrow = lane & 15, lkh = lane >> 4;

    for (int c = 0; c < 16; c++) {
        int k0 = c * 64;
        for (int i = t; i < 1024; i += 256) {
            int row = i >> 3, cv = i & 7;
            uint32_t so = (uint32_t)(row * SSTR + cv * 8);
            size_t ga = (size_t)(m0 + row) * DMODEL + k0 + cv * 8;
            size_t gb = (size_t)(n0 + row) * DMODEL + k0 + cv * 8;
            *(uint4*)(sAh + so) = *(const uint4*)(Ah + ga);
            *(uint4*)(sAl + so) = *(const uint4*)(Al + ga);
            *(uint4*)(sBh + so) = *(const uint4*)(Bh + gb);
            *(uint4*)(sBl + so) = *(const uint4*)(Bl + gb);
        }
        __syncthreads();

#pragma unroll
        for (int pass = 0; pass < 3; pass++) {
            uint32_t uA = (pass == 2) ? uAl : uAh;
            uint32_t uB = (pass == 1) ? uBl : uBh;
#pragma unroll
            for (int ks = 0; ks < 4; ks++) {
                int kk = ks * 16;
                uint32_t a[2][4];
#pragma unroll
                for (int mi = 0; mi < 2; mi++)
                    ldsm_x4(a[mi], uA + 2u * (uint32_t)(
                        (wm0 + mi * 16 + lrow) * SSTR + kk + lkh * 8));
                uint32_t bfr[4][4];
#pragma unroll
                for (int nt = 0; nt < 4; nt++)
                    ldsm_x4(bfr[nt], uB + 2u * (uint32_t)(
                        (wn0 + nt * 16 + lrow) * SSTR + kk + lkh * 8));
#pragma unroll
                for (int mi = 0; mi < 2; mi++)
#pragma unroll
                    for (int nt = 0; nt < 4; nt++) {
                        uint32_t b0[2] = {bfr[nt][0], bfr[nt][2]};
                        uint32_t b1[2] = {bfr[nt][1], bfr[nt][3]};
                        mma_bf16(acc[mi][nt * 2 + 0], a[mi], b0);
                        mma_bf16(acc[mi][nt * 2 + 1], a[mi], b1);
                    }
            }
        }
        __syncthreads();
    }

    // epilogue
    const int lr = lane >> 2, lc = (lane & 3) * 2;
#pragma unroll
    for (int mi = 0; mi < 2; mi++) {
#pragma unroll
        for (int half = 0; half < 2; half++) {
            int m = m0 + wm0 + mi * 16 + lr + half * 8;
#pragma unroll
            for (int ni = 0; ni < 8; ni++) {
                int n = n0 + wn0 + ni * 8 + lc;
                float f0 = acc[mi][ni][half * 2 + 0] * scale;
                float f1 = acc[mi][ni][half * 2 + 1] * scale;
                if (mode == 0) {
                    float2 v; v.x = f0; v.y = f1;
                    *(float2*)(Cf + (size_t)m * DMODEL + n) = v;
                } else {
                    __nv_bfloat162 hp, lp;
                    split2(f0, f1, hp, lp);
                    int b = m >> 11, s = m & 2047, h = n >> 6, d = n & 63;
                    if (mode == 1) {
                        size_t o = (((size_t)(b * HEADS + h)) * S_LEN + s) * DKV + d;
                        *(__nv_bfloat162*)(Ch + o) = hp;
                        *(__nv_bfloat162*)(Cl + o) = lp;
                    } else {
                        size_t o = (((size_t)(b * HEADS + h)) * DKV + d) * S_LEN + s;
                        Ch[o] = __low2bfloat16(hp);  Ch[o + S_LEN] = __high2bfloat16(hp);
                        Cl[o] = __low2bfloat16(lp);  Cl[o + S_LEN] = __high2bfloat16(lp);
                    }
                }
            }
        }
    }
}

// ---------------- HMMA flash attention ----------------
// grid (S/64, B*H), 128 threads (4 warps, warp w owns q rows w*16..w*16+15)
#define ASTR 72
__global__ __launch_bounds__(128) void attn_hmma(const int* __restrict__ mask) {
    extern __shared__ char sma[];
    __nv_bfloat16* sKh = (__nv_bfloat16*)sma;       // 64 x ASTR
    __nv_bfloat16* sKl = sKh + 64 * ASTR;
    __nv_bfloat16* sVh = sKl + 64 * ASTR;           // Vt tiles [d][kv]
    __nv_bfloat16* sVl = sVh + 64 * ASTR;
    float* sBias = (float*)(sVl + 64 * ASTR);       // 2112
    float* sMask = sBias + 2112;                    // 2048

    const int t = threadIdx.x, warp = t >> 5, lane = t & 31;
    const int q0 = blockIdx.x * 64, bh = blockIdx.y;
    const int b = bh >> 4, h = bh & 15;

    // per-CTA bias slice: sBias[i] = bias[h][delta=i-q0-63]
    for (int i = t; i < 2111; i += 128)
        sBias[i] = g_bias[h * NPOS + i - q0 + 1984];
    for (int i = t; i < 2048; i += 128)
        sMask[i] = mask[b * S_LEN + i] ? 0.f : -1e30f;

    const uint32_t uKh = smem_u32(sKh), uKl = smem_u32(sKl);
    const uint32_t uVh = smem_u32(sVh), uVl = smem_u32(sVl);
    const int lrow = lane & 15, lkh = lane >> 4;
    const int lr = lane >> 2, lc2 = (lane & 3) * 2;

    // stage Q via K buffers, grab fragments, release
    {
        const __nv_bfloat16* Qh = g_qh + ((size_t)bh * S_LEN + q0) * DKV;
        const __nv_bfloat16* Ql = g_ql + ((size_t)bh * S_LEN + q0) * DKV;
        for (int i = t; i < 512; i += 128) {
            int row = i >> 3, cv = i & 7;
            *(uint4*)(sKh + row * ASTR + cv * 8) = *(const uint4*)(Qh + row * 64 + cv * 8);
            *(uint4*)(sKl + row * ASTR + cv * 8) = *(const uint4*)(Ql + row * 64 + cv * 8);
        }
    }
    __syncthreads();
    uint32_t qh[4][4], ql[4][4];
#pragma unroll
    for (int ks = 0; ks < 4; ks++) {
        uint32_t ad = 2u * (uint32_t)((warp * 16 + lrow) * ASTR + ks * 16 + lkh * 8);
        ldsm_x4(qh[ks], uKh + ad);
        ldsm_x4(ql[ks], uKl + ad);
    }
    __syncthreads();

    float m_[2] = {-INFINITY, -INFINITY}, l_[2] = {0.f, 0.f};
    float o[8][4];
#pragma unroll
    for (int ni = 0; ni < 8; ni++)
#pragma unroll
        for (int j = 0; j < 4; j++) o[ni][j] = 0.f;

    const __nv_bfloat16* Kh0 = g_kh + (size_t)bh * S_LEN * DKV;
    const __nv_bfloat16* Kl0 = g_kl + (size_t)bh * S_LEN * DKV;
    const __nv_bfloat16* Vh0 = g_vth + (size_t)bh * DKV * S_LEN;
    const __nv_bfloat16* Vl0 = g_vtl + (size_t)bh * DKV * S_LEN;

    for (int kt = 0; kt < S_LEN / 64; kt++) {
        int kb = kt * 64;
        for (int i = t; i < 512; i += 128) {
            int row = i >> 3, cv = i & 7;
            uint32_t so = (uint32_t)(row * ASTR + cv * 8);
            *(uint4*)(sKh + so) = *(const uint4*)(Kh0 + (size_t)(kb + row) * 64 + cv * 8);
            *(uint4*)(sKl + so) = *(const uint4*)(Kl0 + (size_t)(kb + row) * 64 + cv * 8);
            *(uint4*)(sVh + so) = *(const uint4*)(Vh0 + (size_t)row * S_LEN + kb + cv * 8);
            *(uint4*)(sVl + so) = *(const uint4*)(Vl0 + (size_t)row * S_LEN + kb + cv * 8);
        }
        __syncthreads();

        // S = Q K^T (bf16x3)
        float sc[8][4];
#pragma unroll
        for (int ni = 0; ni < 8; ni++)
#pragma unroll
            for (int j = 0; j < 4; j++) sc[ni][j] = 0.f;
#pragma unroll
        for (int ks = 0; ks < 4; ks++) {
            uint32_t kh_[4][4], kl_[4][4];
#pragma unroll
            for (int nt = 0; nt < 4; nt++) {
                uint32_t ad = 2u * (uint32_t)((nt * 16 + lrow) * ASTR + ks * 16 + lkh * 8);
                ldsm_x4(kh_[nt], uKh + ad);
                ldsm_x4(kl_[nt], uKl + ad);
            }
#pragma unroll
            for (int nt = 0; nt < 4; nt++) {
                uint32_t b0h[2] = {kh_[nt][0], kh_[nt][2]}, b1h[2] = {kh_[nt][1], kh_[nt][3]};
                uint32_t b0l[2] = {kl_[nt][0], kl_[nt][2]}, b1l[2] = {kl_[nt][1], kl_[nt][3]};
                mma_bf16(sc[nt * 2 + 0], qh[ks], b0h);
                mma_bf16(sc[nt * 2 + 1], qh[ks], b1h);
                mma_bf16(sc[nt * 2 + 0], qh[ks], b0l);
                mma_bf16(sc[nt * 2 + 1], qh[ks], b1l);
                mma_bf16(sc[nt * 2 + 0], ql[ks], b0h);
                mma_bf16(sc[nt * 2 + 1], ql[ks], b1h);
            }
        }

        // bias + mask + online softmax (rows lr, lr+8 within warp tile)
#pragma unroll
        for (int half = 0; half < 2; half++) {
            int rl = warp * 16 + lr + half * 8;
            float tm = -INFINITY;
#pragma unroll
            for (int ni = 0; ni < 8; ni++) {
#pragma unroll
                for (int jc = 0; jc < 2; jc++) {
                    int cl = ni * 8 + lc2 + jc;
                    float v = sc[ni][half * 2 + jc]
                            + sBias[kb + cl - rl + 63] + sMask[kb + cl];
                    sc[ni][half * 2 + jc] = v;
                    tm = fmaxf(tm, v);
                }
            }
            tm = fmaxf(tm, __shfl_xor_sync(0xffffffffu, tm, 1));
            tm = fmaxf(tm, __shfl_xor_sync(0xffffffffu, tm, 2));
            float mnew = fmaxf(m_[half], tm);
            float alpha = __expf(m_[half] - mnew);
            float rs = 0.f;
#pragma unroll
            for (int ni = 0; ni < 8; ni++) {
#pragma unroll
                for (int jc = 0; jc < 2; jc++) {
                    float p = __expf(sc[ni][half * 2 + jc] - mnew);
                    sc[ni][half * 2 + jc] = p;
                    rs += p;
                }
            }
            rs += __shfl_xor_sync(0xffffffffu, rs, 1);
            rs += __shfl_xor_sync(0xffffffffu, rs, 2);
            l_[half] = l_[half] * alpha + rs;
            m_[half] = mnew;
#pragma unroll
            for (int ni = 0; ni < 8; ni++) {
                o[ni][half * 2 + 0] *= alpha;
                o[ni][half * 2 + 1] *= alpha;
            }
        }

        // O += P V  (P fragments built in-register from sc; bf16x3)
#pragma unroll
        for (int ks = 0; ks < 4; ks++) {
            uint32_t ph[4], pl[4];
#pragma unroll
            for (int q = 0; q < 4; q++) {
                int ni = ks * 2 + (q >> 1);
                int ci = (q & 1) * 2;
                __nv_bfloat162 hp, lp;
                split2(sc[ni][ci], sc[ni][ci + 1], hp, lp);
                ph[q] = reinterpret_cast<uint32_t&>(hp);
                pl[q] = reinterpret_cast<uint32_t&>(lp);
            }
            uint32_t vh_[4][4], vl_[4][4];
#pragma unroll
            for (int nt = 0; nt < 4; nt++) {
                uint32_t ad = 2u * (uint32_t)((nt * 16 + lrow) * ASTR + ks * 16 + lkh * 8);
                ldsm_x4(vh_[nt], uVh + ad);
                ldsm_x4(vl_[nt], uVl + ad);
            }
#pragma unroll
            for (int nt = 0; nt < 4; nt++) {
                uint32_t b0h[2] = {vh_[nt][0], vh_[nt][2]}, b1h[2] = {vh_[nt][1], vh_[nt][3]};
                uint32_t b0l[2] = {vl_[nt][0], vl_[nt][2]}, b1l[2] = {vl_[nt][1], vl_[nt][3]};
                mma_bf16(o[nt * 2 + 0], ph, b0h);
                mma_bf16(o[nt * 2 + 1], ph, b1h);
                mma_bf16(o[nt * 2 + 0], ph, b0l);
                mma_bf16(o[nt * 2 + 1], ph, b1l);
                mma_bf16(o[nt * 2 + 0], pl, b0h);
                mma_bf16(o[nt * 2 + 1], pl, b1h);
            }
        }
        __syncthreads();
    }

    // epilogue: write bf16 hi/lo attn output [B,S,H*Dk]
#pragma unroll
    for (int half = 0; half < 2; half++) {
        int srow = q0 + warp * 16 + lr + half * 8;
        float inv = 1.f / l_[half];
        size_t base = ((size_t)b * S_LEN + srow) * DMODEL + h * 64;
#pragma unroll
        for (int ni = 0; ni < 8; ni++) {
            float f0 = o[ni][half * 2 + 0] * inv;
            float f1 = o[ni][half * 2 + 1] * inv;
            __nv_bfloat162 hp, lp;
            split2(f0, f1, hp, lp);
            *(__nv_bfloat162*)(g_aoh + base + ni * 8 + lc2) = hp;
            *(__nv_bfloat162*)(g_aol + base + ni * 8 + lc2) = lp;
        }
    }
}

// ---------------- launch ----------------
extern "C" void kernel_launch(void* const* d_in, const int* in_sizes, int n_in,
                              void* d_out, int out_size) {
    const float* hidden   = (const float*)d_in[0];
    const int*   mask     = (const int*)  d_in[1];
    const float* Wq       = (const float*)d_in[2];
    const float* Wk       = (const float*)d_in[3];
    const float* Wv       = (const float*)d_in[4];
    const float* Wo       = (const float*)d_in[5];
    const float* rel_bias = (const float*)d_in[6];
    float* out = (float*)d_out;

    __nv_bfloat16 *pxh, *pxl, *pwh, *pwl, *pqh, *pql, *pkh, *pkl,
                  *pvth, *pvtl, *paoh, *paol;
    cudaGetSymbolAddress((void**)&pxh,  g_xh);
    cudaGetSymbolAddress((void**)&pxl,  g_xl);
    cudaGetSymbolAddress((void**)&pwh,  g_wh);
    cudaGetSymbolAddress((void**)&pwl,  g_wl);
    cudaGetSymbolAddress((void**)&pqh,  g_qh);
    cudaGetSymbolAddress((void**)&pql,  g_ql);
    cudaGetSymbolAddress((void**)&pkh,  g_kh);
    cudaGetSymbolAddress((void**)&pkl,  g_kl);
    cudaGetSymbolAddress((void**)&pvth, g_vth);
    cudaGetSymbolAddress((void**)&pvtl, g_vtl);
    cudaGetSymbolAddress((void**)&paoh, g_aoh);
    cudaGetSymbolAddress((void**)&paol, g_aol);

    // 1) bias table
    bias_table_kernel<<<(HEADS * NPOS + 255) / 256, 256>>>(rel_bias);

    // 2) split hidden; transpose+split weights
    int nX = MTOT * DMODEL;
    split_hl_kernel<<<nX / 4 / 256, 256>>>(hidden, pxh, pxl, nX);
    dim3 tg(32, 32), tb(32, 8);
    const size_t WSZ = (size_t)DMODEL * DMODEL;
    transpose_split_kernel<<<tg, tb>>>(Wq, pwh + 0*WSZ, pwl + 0*WSZ);
    transpose_split_kernel<<<tg, tb>>>(Wk, pwh + 1*WSZ, pwl + 1*WSZ);
    transpose_split_kernel<<<tg, tb>>>(Wv, pwh + 2*WSZ, pwl + 2*WSZ);
    transpose_split_kernel<<<tg, tb>>>(Wo, pwh + 3*WSZ, pwl + 3*WSZ);

    // 3) QKV projections on HMMA (bf16x3), epilogue writes bf16 hi/lo layouts
    int gsmem = 4 * 128 * SSTR * (int)sizeof(__nv_bfloat16);  // 73728
    cudaFuncSetAttribute(hmma_gemm, cudaFuncAttributeMaxDynamicSharedMemorySize, gsmem);
    dim3 gg(DMODEL / 128, MTOT / 128);  // (8, 32)
    hmma_gemm<<<gg, 256, gsmem>>>(pxh, pxl, pwh + 0*WSZ, pwl + 0*WSZ,
                                  nullptr, pqh, pql, 0.125f, 1);
    hmma_gemm<<<gg, 256, gsmem>>>(pxh, pxl, pwh + 1*WSZ, pwl + 1*WSZ,
                                  nullptr, pkh, pkl, 1.0f, 1);
    hmma_gemm<<<gg, 256, gsmem>>>(pxh, pxl, pwh + 2*WSZ, pwl + 2*WSZ,
                                  nullptr, pvth, pvtl, 1.0f, 2);

    // 4) HMMA flash attention
    int asmem = 4 * 64 * ASTR * (int)sizeof(__nv_bfloat16)
              + (2112 + 2048) * (int)sizeof(float);            // 53504
    cudaFuncSetAttribute(attn_hmma, cudaFuncAttributeMaxDynamicSharedMemorySize, asmem);
    attn_hmma<<<dim3(S_LEN / 64, BATCH * HEADS), 128, asmem>>>(mask);

    // 5) output projection on HMMA -> fp32 d_out
    hmma_gemm<<<gg, 256, gsmem>>>(paoh, paol, pwh + 3*WSZ, pwl + 3*WSZ,
                                  out, nullptr, nullptr, 1.0f, 0);
}

// round 5
// speedup vs baseline: 2.4602x; 1.1259x over previous
#include <cuda_runtime.h>
#include <cuda_bf16.h>
#include <math.h>
#include <stdint.h>

#define S_LEN 2048
#define BATCH 2
#define HEADS 16
#define DKV 64
#define DMODEL 1024
#define NPOS (2*S_LEN-1)   // 4095
#define MTOT (BATCH*S_LEN) // 4096

// ---------------- device scratch (no allocations allowed) ----------------
__device__ float g_bias[HEADS*NPOS];             // bias[h][delta+2047]

__device__ __nv_bfloat16 g_xh[MTOT*DMODEL];      // hidden hi
__device__ __nv_bfloat16 g_xl[MTOT*DMODEL];      // hidden lo
__device__ __nv_bfloat16 g_wh[4*DMODEL*DMODEL];  // Wq,Wk,Wv,Wo transposed [N,K] hi
__device__ __nv_bfloat16 g_wl[4*DMODEL*DMODEL];  // lo
__device__ __nv_bfloat16 g_qh[BATCH*HEADS*S_LEN*DKV];  // [B,H,S,Dk], scaled 1/8
__device__ __nv_bfloat16 g_ql[BATCH*HEADS*S_LEN*DKV];
__device__ __nv_bfloat16 g_kh[BATCH*HEADS*S_LEN*DKV];  // [B,H,S,Dk]
__device__ __nv_bfloat16 g_kl[BATCH*HEADS*S_LEN*DKV];
__device__ __nv_bfloat16 g_vth[BATCH*HEADS*DKV*S_LEN]; // [B,H,Dk,S] (V^T)
__device__ __nv_bfloat16 g_vtl[BATCH*HEADS*DKV*S_LEN];
__device__ __nv_bfloat16 g_aoh[MTOT*DMODEL];     // attn out hi [B,S,H*Dk]
__device__ __nv_bfloat16 g_aol[MTOT*DMODEL];     // attn out lo

// ---------------- helpers ----------------
__device__ __forceinline__ uint32_t smem_u32(const void* p) {
    uint32_t a;
    asm("{ .reg .u64 t; cvta.to.shared.u64 t, %1; cvt.u32.u64 %0, t; }"
        : "=r"(a) : "l"(p));
    return a;
}
__device__ __forceinline__ void ldsm_x4(uint32_t* r, uint32_t addr) {
    asm volatile("ldmatrix.sync.aligned.m8n8.x4.shared.b16 {%0,%1,%2,%3}, [%4];"
                 : "=r"(r[0]), "=r"(r[1]), "=r"(r[2]), "=r"(r[3]) : "r"(addr));
}
__device__ __forceinline__ void mma_bf16(float* d, const uint32_t* a,
                                         const uint32_t* b) {
    asm volatile(
        "mma.sync.aligned.m16n8k16.row.col.f32.bf16.bf16.f32 "
        "{%0,%1,%2,%3}, {%4,%5,%6,%7}, {%8,%9}, {%0,%1,%2,%3};"
        : "+f"(d[0]), "+f"(d[1]), "+f"(d[2]), "+f"(d[3])
        : "r"(a[0]), "r"(a[1]), "r"(a[2]), "r"(a[3]), "r"(b[0]), "r"(b[1]));
}
__device__ __forceinline__ void split2(float f0, float f1,
                                       __nv_bfloat162& hp, __nv_bfloat162& lp) {
    hp = __floats2bfloat162_rn(f0, f1);
    float2 hf = __bfloat1622float2(hp);
    lp = __floats2bfloat162_rn(f0 - hf.x, f1 - hf.y);
}
__device__ __forceinline__ void cp16(uint32_t s, const void* g) {
    asm volatile("cp.async.cg.shared.global [%0], [%1], 16;" :: "r"(s), "l"(g));
}
__device__ __forceinline__ void cp_commit() {
    asm volatile("cp.async.commit_group;" ::: "memory");
}
__device__ __forceinline__ void cp_wait1() {
    asm volatile("cp.async.wait_group 1;" ::: "memory");
}
__device__ __forceinline__ void cp_wait0() {
    asm volatile("cp.async.wait_group 0;" ::: "memory");
}

// ---------------- relative position bias table ----------------
__global__ void bias_table_kernel(const float* __restrict__ rel_bias) {
    int idx = blockIdx.x * blockDim.x + threadIdx.x;
    if (idx >= HEADS * NPOS) return;
    int h = idx / NPOS;
    int delta = (idx % NPOS) - (S_LEN - 1);
    int ad = delta < 0 ? -delta : delta;
    int bucket = (delta > 0) ? 16 : 0;
    if (ad < 8) {
        bucket += ad;
    } else {
        int lg = 31 - __clz(ad * ad);      // floor(2*log2(ad))
        int bl = lg + 2;
        bucket += (bl > 15) ? 15 : bl;
    }
    g_bias[idx] = rel_bias[bucket * HEADS + h];
}

// ---------------- fp32 -> bf16 hi/lo split ----------------
__global__ void split_hl_kernel(const float* __restrict__ x,
                                __nv_bfloat16* __restrict__ hi,
                                __nv_bfloat16* __restrict__ lo, int n) {
    int i = (blockIdx.x * blockDim.x + threadIdx.x) * 4;
    if (i >= n) return;
    float4 v = *(const float4*)(x + i);
    __nv_bfloat162 h0, l0, h1, l1;
    split2(v.x, v.y, h0, l0);
    split2(v.z, v.w, h1, l1);
    __nv_bfloat162* hp = (__nv_bfloat162*)(hi + i);
    __nv_bfloat162* lp = (__nv_bfloat162*)(lo + i);
    hp[0] = h0; hp[1] = h1;
    lp[0] = l0; lp[1] = l1;
}

// ---------------- transpose + split W[K,N] -> T[N,K] hi/lo ----------------
__global__ void transpose_split_kernel(const float* __restrict__ W,
                                       __nv_bfloat16* __restrict__ Th,
                                       __nv_bfloat16* __restrict__ Tl) {
    __shared__ float tile[32][33];
    int n0 = blockIdx.x * 32, k0 = blockIdx.y * 32;
    int tx = threadIdx.x, ty = threadIdx.y;
    for (int r = ty; r < 32; r += 8)
        tile[r][tx] = W[(size_t)(k0 + r) * DMODEL + n0 + tx];
    __syncthreads();
    for (int r = ty; r < 32; r += 8) {
        float v = tile[tx][r];     // = W[k0+tx][n0+r]
        __nv_bfloat16 h = __float2bfloat16(v);
        __nv_bfloat16 l = __float2bfloat16(v - __bfloat162float(h));
        size_t o = (size_t)(n0 + r) * DMODEL + k0 + tx;
        Th[o] = h; Tl[o] = l;
    }
}

// ---------------- HMMA bf16x3 GEMM, cp.async 2-stage ----------------
// C[4096,1024] = A[4096,1024] @ B^T  (B stored [N,K] K-major)
// CTA 128x128 tile, BK=32, 8 warps (4m x 2n), warp tile 32x64.
// mode 0: fp32 row-major; mode 1: bf16 hi/lo [B,H,S,Dk]; mode 2: bf16 hi/lo [B,H,Dk,S]
#define SSTR 40            // smem row stride in bf16 (32 + 8 pad)
#define GBUF (128*SSTR)    // elements per buffer (5120)
__global__ __launch_bounds__(256) void hmma_gemm(
    const __nv_bfloat16* __restrict__ Ah, const __nv_bfloat16* __restrict__ Al,
    const __nv_bfloat16* __restrict__ Bh, const __nv_bfloat16* __restrict__ Bl,
    float* __restrict__ Cf, __nv_bfloat16* __restrict__ Ch,
    __nv_bfloat16* __restrict__ Cl, float scale, int mode)
{
    extern __shared__ __nv_bfloat16 sm16[];
    const int t = threadIdx.x, wid = t >> 5, lane = t & 31;
    const int m0 = blockIdx.y * 128, n0 = blockIdx.x * 128;
    const int wm0 = (wid & 3) * 32;
    const int wn0 = (wid >> 2) * 64;
    const uint32_t ub = smem_u32(sm16);

    float acc[2][8][4];
#pragma unroll
    for (int mi = 0; mi < 2; mi++)
#pragma unroll
        for (int ni = 0; ni < 8; ni++)
#pragma unroll
            for (int j = 0; j < 4; j++) acc[mi][ni][j] = 0.f;

    const int lrow = lane & 15, lkh = lane >> 4;

    // issue loads for chunk c into stage s
    auto issue = [&](int c, int s) {
        int k0 = c * 32;
        uint32_t sb = ub + (uint32_t)s * (4 * GBUF * 2);
#pragma unroll
        for (int rep = 0; rep < 2; rep++) {
            int i = t + rep * 256;              // 0..511
            int row = i >> 2, cv = i & 3;
            uint32_t so = sb + (uint32_t)(row * SSTR + cv * 8) * 2;
            const __nv_bfloat16* pa = Ah + (size_t)(m0 + row) * DMODEL + k0 + cv * 8;
            const __nv_bfloat16* pal = Al + (size_t)(m0 + row) * DMODEL + k0 + cv * 8;
            const __nv_bfloat16* pb = Bh + (size_t)(n0 + row) * DMODEL + k0 + cv * 8;
            const __nv_bfloat16* pbl = Bl + (size_t)(n0 + row) * DMODEL + k0 + cv * 8;
            cp16(so,                pa);
            cp16(so + GBUF * 2,     pal);
            cp16(so + 2 * GBUF * 2, pb);
            cp16(so + 3 * GBUF * 2, pbl);
        }
        cp_commit();
    };

    issue(0, 0);
    for (int c = 0; c < 32; c++) {
        if (c < 31) { issue(c + 1, (c + 1) & 1); cp_wait1(); }
        else cp_wait0();
        __syncthreads();

        uint32_t sb = ub + (uint32_t)(c & 1) * (4 * GBUF * 2);
#pragma unroll
        for (int pass = 0; pass < 3; pass++) {
            uint32_t uA = sb + ((pass == 2) ? GBUF * 2 : 0);
            uint32_t uB = sb + 2 * GBUF * 2 + ((pass == 1) ? GBUF * 2 : 0);
#pragma unroll
            for (int ks = 0; ks < 2; ks++) {
                int kk = ks * 16;
                uint32_t a[2][4];
#pragma unroll
                for (int mi = 0; mi < 2; mi++)
                    ldsm_x4(a[mi], uA + 2u * (uint32_t)(
                        (wm0 + mi * 16 + lrow) * SSTR + kk + lkh * 8));
                uint32_t bfr[4][4];
#pragma unroll
                for (int nt = 0; nt < 4; nt++)
                    ldsm_x4(bfr[nt], uB + 2u * (uint32_t)(
                        (wn0 + nt * 16 + lrow) * SSTR + kk + lkh * 8));
#pragma unroll
                for (int mi = 0; mi < 2; mi++)
#pragma unroll
                    for (int nt = 0; nt < 4; nt++) {
                        uint32_t b0[2] = {bfr[nt][0], bfr[nt][2]};
                        uint32_t b1[2] = {bfr[nt][1], bfr[nt][3]};
                        mma_bf16(acc[mi][nt * 2 + 0], a[mi], b0);
                        mma_bf16(acc[mi][nt * 2 + 1], a[mi], b1);
                    }
            }
        }
        __syncthreads();
    }

    // epilogue
    const int lr = lane >> 2, lc = (lane & 3) * 2;
#pragma unroll
    for (int mi = 0; mi < 2; mi++) {
#pragma unroll
        for (int half = 0; half < 2; half++) {
            int m = m0 + wm0 + mi * 16 + lr + half * 8;
#pragma unroll
            for (int ni = 0; ni < 8; ni++) {
                int n = n0 + wn0 + ni * 8 + lc;
                float f0 = acc[mi][ni][half * 2 + 0] * scale;
                float f1 = acc[mi][ni][half * 2 + 1] * scale;
                if (mode == 0) {
                    float2 v; v.x = f0; v.y = f1;
                    *(float2*)(Cf + (size_t)m * DMODEL + n) = v;
                } else {
                    __nv_bfloat162 hp, lp;
                    split2(f0, f1, hp, lp);
                    int b = m >> 11, s = m & 2047, h = n >> 6, d = n & 63;
                    if (mode == 1) {
                        size_t o = (((size_t)(b * HEADS + h)) * S_LEN + s) * DKV + d;
                        *(__nv_bfloat162*)(Ch + o) = hp;
                        *(__nv_bfloat162*)(Cl + o) = lp;
                    } else {
                        size_t o = (((size_t)(b * HEADS + h)) * DKV + d) * S_LEN + s;
                        Ch[o] = __low2bfloat16(hp);  Ch[o + S_LEN] = __high2bfloat16(hp);
                        Cl[o] = __low2bfloat16(lp);  Cl[o + S_LEN] = __high2bfloat16(lp);
                    }
                }
            }
        }
    }
}

// ---------------- HMMA flash attention, cp.async 2-stage ----------------
// grid (S/64, B*H), 128 threads (4 warps, warp w owns q rows w*16..w*16+15)
#define ASTR 72
#define ABUF (64*ASTR)     // elements per buffer (4608)
__global__ __launch_bounds__(128) void attn_hmma(const int* __restrict__ mask) {
    extern __shared__ char sma[];
    __nv_bfloat16* stage = (__nv_bfloat16*)sma;      // 2 stages x {Kh,Kl,Vh,Vl}
    float* sBias = (float*)(stage + 2 * 4 * ABUF);   // 2112
    float* sMask = sBias + 2112;                     // 2048

    const int t = threadIdx.x, warp = t >> 5, lane = t & 31;
    const int q0 = blockIdx.x * 64, bh = blockIdx.y;
    const int b = bh >> 4, h = bh & 15;

    for (int i = t; i < 2111; i += 128)
        sBias[i] = g_bias[h * NPOS + i - q0 + 1984];
    for (int i = t; i < 2048; i += 128)
        sMask[i] = mask[b * S_LEN + i] ? 0.f : -1e30f;

    const uint32_t uS = smem_u32(stage);
    const int lrow = lane & 15, lkh = lane >> 4;
    const int lr = lane >> 2, lc2 = (lane & 3) * 2;

    const __nv_bfloat16* Kh0 = g_kh + (size_t)bh * S_LEN * DKV;
    const __nv_bfloat16* Kl0 = g_kl + (size_t)bh * S_LEN * DKV;
    const __nv_bfloat16* Vh0 = g_vth + (size_t)bh * DKV * S_LEN;
    const __nv_bfloat16* Vl0 = g_vtl + (size_t)bh * DKV * S_LEN;

    // stage Q via stage-0 Kh/Kl slots, grab fragments, release
    {
        const __nv_bfloat16* Qh = g_qh + ((size_t)bh * S_LEN + q0) * DKV;
        const __nv_bfloat16* Ql = g_ql + ((size_t)bh * S_LEN + q0) * DKV;
        for (int i = t; i < 512; i += 128) {
            int row = i >> 3, cv = i & 7;
            *(uint4*)(stage + row * ASTR + cv * 8) =
                *(const uint4*)(Qh + row * 64 + cv * 8);
            *(uint4*)(stage + ABUF + row * ASTR + cv * 8) =
                *(const uint4*)(Ql + row * 64 + cv * 8);
        }
    }
    __syncthreads();
    uint32_t qh[4][4], ql[4][4];
#pragma unroll
    for (int ks = 0; ks < 4; ks++) {
        uint32_t ad = 2u * (uint32_t)((warp * 16 + lrow) * ASTR + ks * 16 + lkh * 8);
        ldsm_x4(qh[ks], uS + ad);
        ldsm_x4(ql[ks], uS + ABUF * 2 + ad);
    }
    __syncthreads();

    auto issueKV = [&](int kt, int s) {
        int kb = kt * 64;
        uint32_t sb = uS + (uint32_t)s * (4 * ABUF * 2);
#pragma unroll
        for (int rep = 0; rep < 4; rep++) {
            int i = t + rep * 128;             // 0..511
            int row = i >> 3, cv = i & 7;
            uint32_t so = sb + (uint32_t)(row * ASTR + cv * 8) * 2;
            cp16(so,                Kh0 + (size_t)(kb + row) * 64 + cv * 8);
            cp16(so + ABUF * 2,     Kl0 + (size_t)(kb + row) * 64 + cv * 8);
            cp16(so + 2 * ABUF * 2, Vh0 + (size_t)row * S_LEN + kb + cv * 8);
            cp16(so + 3 * ABUF * 2, Vl0 + (size_t)row * S_LEN + kb + cv * 8);
        }
        cp_commit();
    };

    float m_[2] = {-INFINITY, -INFINITY}, l_[2] = {0.f, 0.f};
    float o[8][4];
#pragma unroll
    for (int ni = 0; ni < 8; ni++)
#pragma unroll
        for (int j = 0; j < 4; j++) o[ni][j] = 0.f;

    issueKV(0, 0);
    for (int kt = 0; kt < S_LEN / 64; kt++) {
        int kb = kt * 64;
        if (kt < 31) { issueKV(kt + 1, (kt + 1) & 1); cp_wait1(); }
        else cp_wait0();
        __syncthreads();

        uint32_t sb = uS + (uint32_t)(kt & 1) * (4 * ABUF * 2);
        uint32_t uKh = sb, uKl = sb + ABUF * 2;
        uint32_t uVh = sb + 2 * ABUF * 2, uVl = sb + 3 * ABUF * 2;

        // S = Q K^T (bf16x3)
        float sc[8][4];
#pragma unroll
        for (int ni = 0; ni < 8; ni++)
#pragma unroll
            for (int j = 0; j < 4; j++) sc[ni][j] = 0.f;
#pragma unroll
        for (int ks = 0; ks < 4; ks++) {
            uint32_t kh_[4][4], kl_[4][4];
#pragma unroll
            for (int nt = 0; nt < 4; nt++) {
                uint32_t ad = 2u * (uint32_t)((nt * 16 + lrow) * ASTR + ks * 16 + lkh * 8);
                ldsm_x4(kh_[nt], uKh + ad);
                ldsm_x4(kl_[nt], uKl + ad);
            }
#pragma unroll
            for (int nt = 0; nt < 4; nt++) {
                uint32_t b0h[2] = {kh_[nt][0], kh_[nt][2]}, b1h[2] = {kh_[nt][1], kh_[nt][3]};
                uint32_t b0l[2] = {kl_[nt][0], kl_[nt][2]}, b1l[2] = {kl_[nt][1], kl_[nt][3]};
                mma_bf16(sc[nt * 2 + 0], qh[ks], b0h);
                mma_bf16(sc[nt * 2 + 1], qh[ks], b1h);
                mma_bf16(sc[nt * 2 + 0], qh[ks], b0l);
                mma_bf16(sc[nt * 2 + 1], qh[ks], b1l);
                mma_bf16(sc[nt * 2 + 0], ql[ks], b0h);
                mma_bf16(sc[nt * 2 + 1], ql[ks], b1h);
            }
        }

        // bias + mask + online softmax
#pragma unroll
        for (int half = 0; half < 2; half++) {
            int rl = warp * 16 + lr + half * 8;
            float tm = -INFINITY;
#pragma unroll
            for (int ni = 0; ni < 8; ni++) {
#pragma unroll
                for (int jc = 0; jc < 2; jc++) {
                    int cl = ni * 8 + lc2 + jc;
                    float v = sc[ni][half * 2 + jc]
                            + sBias[kb + cl - rl + 63] + sMask[kb + cl];
                    sc[ni][half * 2 + jc] = v;
                    tm = fmaxf(tm, v);
                }
            }
            tm = fmaxf(tm, __shfl_xor_sync(0xffffffffu, tm, 1));
            tm = fmaxf(tm, __shfl_xor_sync(0xffffffffu, tm, 2));
            float mnew = fmaxf(m_[half], tm);
            float alpha = __expf(m_[half] - mnew);
            float rs = 0.f;
#pragma unroll
            for (int ni = 0; ni < 8; ni++) {
#pragma unroll
                for (int jc = 0; jc < 2; jc++) {
                    float p = __expf(sc[ni][half * 2 + jc] - mnew);
                    sc[ni][half * 2 + jc] = p;
                    rs += p;
                }
            }
            rs += __shfl_xor_sync(0xffffffffu, rs, 1);
            rs += __shfl_xor_sync(0xffffffffu, rs, 2);
            l_[half] = l_[half] * alpha + rs;
            m_[half] = mnew;
#pragma unroll
            for (int ni = 0; ni < 8; ni++) {
                o[ni][half * 2 + 0] *= alpha;
                o[ni][half * 2 + 1] *= alpha;
            }
        }

        // O += P V  (P fragments built in-register; bf16x3)
#pragma unroll
        for (int ks = 0; ks < 4; ks++) {
            uint32_t ph[4], pl[4];
#pragma unroll
            for (int q = 0; q < 4; q++) {
                int ni = ks * 2 + (q >> 1);
                int ci = (q & 1) * 2;
                __nv_bfloat162 hp, lp;
                split2(sc[ni][ci], sc[ni][ci + 1], hp, lp);
                ph[q] = reinterpret_cast<uint32_t&>(hp);
                pl[q] = reinterpret_cast<uint32_t&>(lp);
            }
            uint32_t vh_[4][4], vl_[4][4];
#pragma unroll
            for (int nt = 0; nt < 4; nt++) {
                uint32_t ad = 2u * (uint32_t)((nt * 16 + lrow) * ASTR + ks * 16 + lkh * 8);
                ldsm_x4(vh_[nt], uVh + ad);
                ldsm_x4(vl_[nt], uVl + ad);
            }
#pragma unroll
            for (int nt = 0; nt < 4; nt++) {
                uint32_t b0h[2] = {vh_[nt][0], vh_[nt][2]}, b1h[2] = {vh_[nt][1], vh_[nt][3]};
                uint32_t b0l[2] = {vl_[nt][0], vl_[nt][2]}, b1l[2] = {vl_[nt][1], vl_[nt][3]};
                mma_bf16(o[nt * 2 + 0], ph, b0h);
                mma_bf16(o[nt * 2 + 1], ph, b1h);
                mma_bf16(o[nt * 2 + 0], ph, b0l);
                mma_bf16(o[nt * 2 + 1], ph, b1l);
                mma_bf16(o[nt * 2 + 0], pl, b0h);
                mma_bf16(o[nt * 2 + 1], pl, b1h);
            }
        }
        __syncthreads();
    }

    // epilogue: write bf16 hi/lo attn output [B,S,H*Dk]
#pragma unroll
    for (int half = 0; half < 2; half++) {
        int srow = q0 + warp * 16 + lr + half * 8;
        float inv = 1.f / l_[half];
        size_t base = ((size_t)b * S_LEN + srow) * DMODEL + h * 64;
#pragma unroll
        for (int ni = 0; ni < 8; ni++) {
            float f0 = o[ni][half * 2 + 0] * inv;
            float f1 = o[ni][half * 2 + 1] * inv;
            __nv_bfloat162 hp, lp;
            split2(f0, f1, hp, lp);
            *(__nv_bfloat162*)(g_aoh + base + ni * 8 + lc2) = hp;
            *(__nv_bfloat162*)(g_aol + base + ni * 8 + lc2) = lp;
        }
    }
}

// ---------------- launch ----------------
extern "C" void kernel_launch(void* const* d_in, const int* in_sizes, int n_in,
                              void* d_out, int out_size) {
    const float* hidden   = (const float*)d_in[0];
    const int*   mask     = (const int*)  d_in[1];
    const float* Wq       = (const float*)d_in[2];
    const float* Wk       = (const float*)d_in[3];
    const float* Wv       = (const float*)d_in[4];
    const float* Wo       = (const float*)d_in[5];
    const float* rel_bias = (const float*)d_in[6];
    float* out = (float*)d_out;

    __nv_bfloat16 *pxh, *pxl, *pwh, *pwl, *pqh, *pql, *pkh, *pkl,
                  *pvth, *pvtl, *paoh, *paol;
    cudaGetSymbolAddress((void**)&pxh,  g_xh);
    cudaGetSymbolAddress((void**)&pxl,  g_xl);
    cudaGetSymbolAddress((void**)&pwh,  g_wh);
    cudaGetSymbolAddress((void**)&pwl,  g_wl);
    cudaGetSymbolAddress((void**)&pqh,  g_qh);
    cudaGetSymbolAddress((void**)&pql,  g_ql);
    cudaGetSymbolAddress((void**)&pkh,  g_kh);
    cudaGetSymbolAddress((void**)&pkl,  g_kl);
    cudaGetSymbolAddress((void**)&pvth, g_vth);
    cudaGetSymbolAddress((void**)&pvtl, g_vtl);
    cudaGetSymbolAddress((void**)&paoh, g_aoh);
    cudaGetSymbolAddress((void**)&paol, g_aol);

    // 1) bias table
    bias_table_kernel<<<(HEADS * NPOS + 255) / 256, 256>>>(rel_bias);

    // 2) split hidden; transpose+split weights
    int nX = MTOT * DMODEL;
    split_hl_kernel<<<nX / 4 / 256, 256>>>(hidden, pxh, pxl, nX);
    dim3 tg(32, 32), tb(32, 8);
    const size_t WSZ = (size_t)DMODEL * DMODEL;
    transpose_split_kernel<<<tg, tb>>>(Wq, pwh + 0*WSZ, pwl + 0*WSZ);
    transpose_split_kernel<<<tg, tb>>>(Wk, pwh + 1*WSZ, pwl + 1*WSZ);
    transpose_split_kernel<<<tg, tb>>>(Wv, pwh + 2*WSZ, pwl + 2*WSZ);
    transpose_split_kernel<<<tg, tb>>>(Wo, pwh + 3*WSZ, pwl + 3*WSZ);

    // 3) QKV projections on HMMA (bf16x3), 2-stage cp.async
    int gsmem = 2 * 4 * GBUF * (int)sizeof(__nv_bfloat16);   // 81920
    cudaFuncSetAttribute(hmma_gemm, cudaFuncAttributeMaxDynamicSharedMemorySize, gsmem);
    dim3 gg(DMODEL / 128, MTOT / 128);  // (8, 32)
    hmma_gemm<<<gg, 256, gsmem>>>(pxh, pxl, pwh + 0*WSZ, pwl + 0*WSZ,
                                  nullptr, pqh, pql, 0.125f, 1);
    hmma_gemm<<<gg, 256, gsmem>>>(pxh, pxl, pwh + 1*WSZ, pwl + 1*WSZ,
                                  nullptr, pkh, pkl, 1.0f, 1);
    hmma_gemm<<<gg, 256, gsmem>>>(pxh, pxl, pwh + 2*WSZ, pwl + 2*WSZ,
                                  nullptr, pvth, pvtl, 1.0f, 2);

    // 4) HMMA flash attention, 2-stage cp.async
    int asmem = 2 * 4 * ABUF * (int)sizeof(__nv_bfloat16)
              + (2112 + 2048) * (int)sizeof(float);          // 90368
    cudaFuncSetAttribute(attn_hmma, cudaFuncAttributeMaxDynamicSharedMemorySize, asmem);
    attn_hmma<<<dim3(S_LEN / 64, BATCH * HEADS), 128, asmem>>>(mask);

    // 5) output projection on HMMA -> fp32 d_out
    hmma_gemm<<<gg, 256, gsmem>>>(paoh, paol, pwh + 3*WSZ, pwl + 3*WSZ,
                                  out, nullptr, nullptr, 1.0f, 0);
}

// round 6
// speedup vs baseline: 2.5250x; 1.0264x over previous
#include <cuda_runtime.h>
#include <cuda_bf16.h>
#include <math.h>
#include <stdint.h>

#define S_LEN 2048
#define BATCH 2
#define HEADS 16
#define DKV 64
#define DMODEL 1024
#define NPOS (2*S_LEN-1)   // 4095
#define MTOT (BATCH*S_LEN) // 4096

// ---------------- device scratch (no allocations allowed) ----------------
__device__ float g_bias[HEADS*NPOS];             // bias[h][delta+2047]

__device__ __nv_bfloat16 g_xh[MTOT*DMODEL];      // hidden hi
__device__ __nv_bfloat16 g_xl[MTOT*DMODEL];      // hidden lo
__device__ __nv_bfloat16 g_wh[4*DMODEL*DMODEL];  // Wq,Wk,Wv,Wo transposed [N,K] hi
__device__ __nv_bfloat16 g_wl[4*DMODEL*DMODEL];  // lo
__device__ __nv_bfloat16 g_qh[BATCH*HEADS*S_LEN*DKV];  // [B,H,S,Dk], scaled 1/8
__device__ __nv_bfloat16 g_ql[BATCH*HEADS*S_LEN*DKV];
__device__ __nv_bfloat16 g_kh[BATCH*HEADS*S_LEN*DKV];  // [B,H,S,Dk]
__device__ __nv_bfloat16 g_kl[BATCH*HEADS*S_LEN*DKV];
__device__ __nv_bfloat16 g_vth[BATCH*HEADS*DKV*S_LEN]; // [B,H,Dk,S] (V^T)
__device__ __nv_bfloat16 g_vtl[BATCH*HEADS*DKV*S_LEN];
__device__ __nv_bfloat16 g_aoh[MTOT*DMODEL];     // attn out hi [B,S,H*Dk]
__device__ __nv_bfloat16 g_aol[MTOT*DMODEL];     // attn out lo

// ---------------- helpers ----------------
__device__ __forceinline__ uint32_t smem_u32(const void* p) {
    uint32_t a;
    asm("{ .reg .u64 t; cvta.to.shared.u64 t, %1; cvt.u32.u64 %0, t; }"
        : "=r"(a) : "l"(p));
    return a;
}
__device__ __forceinline__ void ldsm_x4(uint32_t* r, uint32_t addr) {
    asm volatile("ldmatrix.sync.aligned.m8n8.x4.shared.b16 {%0,%1,%2,%3}, [%4];"
                 : "=r"(r[0]), "=r"(r[1]), "=r"(r[2]), "=r"(r[3]) : "r"(addr));
}
__device__ __forceinline__ void mma_bf16(float* d, const uint32_t* a,
                                         const uint32_t* b) {
    asm volatile(
        "mma.sync.aligned.m16n8k16.row.col.f32.bf16.bf16.f32 "
        "{%0,%1,%2,%3}, {%4,%5,%6,%7}, {%8,%9}, {%0,%1,%2,%3};"
        : "+f"(d[0]), "+f"(d[1]), "+f"(d[2]), "+f"(d[3])
        : "r"(a[0]), "r"(a[1]), "r"(a[2]), "r"(a[3]), "r"(b[0]), "r"(b[1]));
}
__device__ __forceinline__ void split2(float f0, float f1,
                                       __nv_bfloat162& hp, __nv_bfloat162& lp) {
    hp = __floats2bfloat162_rn(f0, f1);
    float2 hf = __bfloat1622float2(hp);
    lp = __floats2bfloat162_rn(f0 - hf.x, f1 - hf.y);
}
__device__ __forceinline__ void cp16(uint32_t s, const void* g) {
    asm volatile("cp.async.cg.shared.global [%0], [%1], 16;" :: "r"(s), "l"(g));
}
__device__ __forceinline__ void cp_commit() {
    asm volatile("cp.async.commit_group;" ::: "memory");
}
__device__ __forceinline__ void cp_wait1() {
    asm volatile("cp.async.wait_group 1;" ::: "memory");
}
__device__ __forceinline__ void cp_wait0() {
    asm volatile("cp.async.wait_group 0;" ::: "memory");
}

// ---------------- relative position bias table ----------------
__global__ void bias_table_kernel(const float* __restrict__ rel_bias) {
    int idx = blockIdx.x * blockDim.x + threadIdx.x;
    if (idx >= HEADS * NPOS) return;
    int h = idx / NPOS;
    int delta = (idx % NPOS) - (S_LEN - 1);
    int ad = delta < 0 ? -delta : delta;
    int bucket = (delta > 0) ? 16 : 0;
    if (ad < 8) {
        bucket += ad;
    } else {
        int lg = 31 - __clz(ad * ad);      // floor(2*log2(ad))
        int bl = lg + 2;
        bucket += (bl > 15) ? 15 : bl;
    }
    g_bias[idx] = rel_bias[bucket * HEADS + h];
}

// ---------------- fp32 -> bf16 hi/lo split ----------------
__global__ void split_hl_kernel(const float* __restrict__ x,
                                __nv_bfloat16* __restrict__ hi,
                                __nv_bfloat16* __restrict__ lo, int n) {
    int i = (blockIdx.x * blockDim.x + threadIdx.x) * 4;
    if (i >= n) return;
    float4 v = *(const float4*)(x + i);
    __nv_bfloat162 h0, l0, h1, l1;
    split2(v.x, v.y, h0, l0);
    split2(v.z, v.w, h1, l1);
    __nv_bfloat162* hp = (__nv_bfloat162*)(hi + i);
    __nv_bfloat162* lp = (__nv_bfloat162*)(lo + i);
    hp[0] = h0; hp[1] = h1;
    lp[0] = l0; lp[1] = l1;
}

// ---------------- transpose + split W[K,N] -> T[N,K] hi/lo ----------------
__global__ void transpose_split_kernel(const float* __restrict__ W,
                                       __nv_bfloat16* __restrict__ Th,
                                       __nv_bfloat16* __restrict__ Tl) {
    __shared__ float tile[32][33];
    int n0 = blockIdx.x * 32, k0 = blockIdx.y * 32;
    int tx = threadIdx.x, ty = threadIdx.y;
    for (int r = ty; r < 32; r += 8)
        tile[r][tx] = W[(size_t)(k0 + r) * DMODEL + n0 + tx];
    __syncthreads();
    for (int r = ty; r < 32; r += 8) {
        float v = tile[tx][r];     // = W[k0+tx][n0+r]
        __nv_bfloat16 h = __float2bfloat16(v);
        __nv_bfloat16 l = __float2bfloat16(v - __bfloat162float(h));
        size_t o = (size_t)(n0 + r) * DMODEL + k0 + tx;
        Th[o] = h; Tl[o] = l;
    }
}

// ---------------- GEMM core: bf16x3, BK=64, 2-stage cp.async ----------------
// acc[2][8][4] = A[m0:m0+128, :] @ B[n0:n0+128, :]^T, register-cached fragments
#define SSTR 72            // smem row stride in bf16 (64 + 8 pad)
#define GBUF (128*SSTR)    // elements per buffer (9216)
__device__ __forceinline__ void gemm_tile(
    const __nv_bfloat16* __restrict__ Ah, const __nv_bfloat16* __restrict__ Al,
    const __nv_bfloat16* __restrict__ Bh, const __nv_bfloat16* __restrict__ Bl,
    int m0, int n0, __nv_bfloat16* sm16, int t, float acc[2][8][4])
{
    const int wid = t >> 5, lane = t & 31;
    const int wm0 = (wid & 3) * 32, wn0 = (wid >> 2) * 64;
    const uint32_t ub = smem_u32(sm16);
    const int lrow = lane & 15, lkh = lane >> 4;

    auto issue = [&](int c, int s) {
        int k0 = c * 64;
        uint32_t sb = ub + (uint32_t)s * (4 * GBUF * 2);
#pragma unroll
        for (int rep = 0; rep < 4; rep++) {
            int i = t + rep * 256;           // 0..1023
            int row = i >> 3, cv = i & 7;
            uint32_t so = sb + (uint32_t)(row * SSTR + cv * 8) * 2;
            size_t ga = (size_t)(m0 + row) * DMODEL + k0 + cv * 8;
            size_t gb = (size_t)(n0 + row) * DMODEL + k0 + cv * 8;
            cp16(so,                Ah + ga);
            cp16(so + GBUF * 2,     Al + ga);
            cp16(so + 2 * GBUF * 2, Bh + gb);
            cp16(so + 3 * GBUF * 2, Bl + gb);
        }
        cp_commit();
    };

    issue(0, 0);
    for (int c = 0; c < 16; c++) {
        if (c < 15) { issue(c + 1, (c + 1) & 1); cp_wait1(); }
        else cp_wait0();
        __syncthreads();

        uint32_t sb = ub + (uint32_t)(c & 1) * (4 * GBUF * 2);
        uint32_t uAh = sb,                uAl = sb + GBUF * 2;
        uint32_t uBh = sb + 2 * GBUF * 2, uBl = sb + 3 * GBUF * 2;
#pragma unroll
        for (int ks = 0; ks < 4; ks++) {
            int kk = ks * 16;
            uint32_t ah[2][4], al[2][4], bh[4][4], bl[4][4];
#pragma unroll
            for (int mi = 0; mi < 2; mi++) {
                uint32_t ad = 2u * (uint32_t)((wm0 + mi * 16 + lrow) * SSTR + kk + lkh * 8);
                ldsm_x4(ah[mi], uAh + ad);
                ldsm_x4(al[mi], uAl + ad);
            }
#pragma unroll
            for (int nt = 0; nt < 4; nt++) {
                uint32_t ad = 2u * (uint32_t)((wn0 + nt * 16 + lrow) * SSTR + kk + lkh * 8);
                ldsm_x4(bh[nt], uBh + ad);
                ldsm_x4(bl[nt], uBl + ad);
            }
#pragma unroll
            for (int mi = 0; mi < 2; mi++)
#pragma unroll
                for (int nt = 0; nt < 4; nt++) {
                    uint32_t b0h[2] = {bh[nt][0], bh[nt][2]}, b1h[2] = {bh[nt][1], bh[nt][3]};
                    uint32_t b0l[2] = {bl[nt][0], bl[nt][2]}, b1l[2] = {bl[nt][1], bl[nt][3]};
                    mma_bf16(acc[mi][nt * 2 + 0], ah[mi], b0h);
                    mma_bf16(acc[mi][nt * 2 + 1], ah[mi], b1h);
                    mma_bf16(acc[mi][nt * 2 + 0], ah[mi], b0l);
                    mma_bf16(acc[mi][nt * 2 + 1], ah[mi], b1l);
                    mma_bf16(acc[mi][nt * 2 + 0], al[mi], b0h);
                    mma_bf16(acc[mi][nt * 2 + 1], al[mi], b1h);
                }
        }
        __syncthreads();
    }
}

// ---------------- merged QKV projection (grid.z selects weight slab) ----------------
__global__ __launch_bounds__(256) void hmma_gemm_qkv(
    const __nv_bfloat16* __restrict__ Ah, const __nv_bfloat16* __restrict__ Al,
    const __nv_bfloat16* __restrict__ Wh, const __nv_bfloat16* __restrict__ Wl,
    __nv_bfloat16* __restrict__ Qh, __nv_bfloat16* __restrict__ Ql,
    __nv_bfloat16* __restrict__ Kh, __nv_bfloat16* __restrict__ Kl,
    __nv_bfloat16* __restrict__ Vth, __nv_bfloat16* __restrict__ Vtl)
{
    extern __shared__ __nv_bfloat16 sm16[];
    const int t = threadIdx.x, wid = t >> 5, lane = t & 31;
    const int m0 = blockIdx.y * 128, n0 = blockIdx.x * 128;
    const int z = blockIdx.z;
    const size_t WSZ = (size_t)DMODEL * DMODEL;

    float acc[2][8][4];
#pragma unroll
    for (int mi = 0; mi < 2; mi++)
#pragma unroll
        for (int ni = 0; ni < 8; ni++)
#pragma unroll
            for (int j = 0; j < 4; j++) acc[mi][ni][j] = 0.f;

    gemm_tile(Ah, Al, Wh + z * WSZ, Wl + z * WSZ, m0, n0, sm16, t, acc);

    const float scale = (z == 0) ? 0.125f : 1.0f;
    const int wm0 = (wid & 3) * 32, wn0 = (wid >> 2) * 64;
    const int lr = lane >> 2, lc = (lane & 3) * 2;
    __nv_bfloat16* Ch = (z == 0) ? Qh : (z == 1) ? Kh : Vth;
    __nv_bfloat16* Cl = (z == 0) ? Ql : (z == 1) ? Kl : Vtl;
#pragma unroll
    for (int mi = 0; mi < 2; mi++) {
#pragma unroll
        for (int half = 0; half < 2; half++) {
            int m = m0 + wm0 + mi * 16 + lr + half * 8;
#pragma unroll
            for (int ni = 0; ni < 8; ni++) {
                int n = n0 + wn0 + ni * 8 + lc;
                float f0 = acc[mi][ni][half * 2 + 0] * scale;
                float f1 = acc[mi][ni][half * 2 + 1] * scale;
                __nv_bfloat162 hp, lp;
                split2(f0, f1, hp, lp);
                int b = m >> 11, s = m & 2047, h = n >> 6, d = n & 63;
                if (z < 2) {
                    size_t o = (((size_t)(b * HEADS + h)) * S_LEN + s) * DKV + d;
                    *(__nv_bfloat162*)(Ch + o) = hp;
                    *(__nv_bfloat162*)(Cl + o) = lp;
                } else {
                    size_t o = (((size_t)(b * HEADS + h)) * DKV + d) * S_LEN + s;
                    Ch[o] = __low2bfloat16(hp);  Ch[o + S_LEN] = __high2bfloat16(hp);
                    Cl[o] = __low2bfloat16(lp);  Cl[o + S_LEN] = __high2bfloat16(lp);
                }
            }
        }
    }
}

// ---------------- output projection -> fp32 ----------------
__global__ __launch_bounds__(256) void hmma_gemm_out(
    const __nv_bfloat16* __restrict__ Ah, const __nv_bfloat16* __restrict__ Al,
    const __nv_bfloat16* __restrict__ Bh, const __nv_bfloat16* __restrict__ Bl,
    float* __restrict__ Cf)
{
    extern __shared__ __nv_bfloat16 sm16[];
    const int t = threadIdx.x, wid = t >> 5, lane = t & 31;
    const int m0 = blockIdx.y * 128, n0 = blockIdx.x * 128;

    float acc[2][8][4];
#pragma unroll
    for (int mi = 0; mi < 2; mi++)
#pragma unroll
        for (int ni = 0; ni < 8; ni++)
#pragma unroll
            for (int j = 0; j < 4; j++) acc[mi][ni][j] = 0.f;

    gemm_tile(Ah, Al, Bh, Bl, m0, n0, sm16, t, acc);

    const int wm0 = (wid & 3) * 32, wn0 = (wid >> 2) * 64;
    const int lr = lane >> 2, lc = (lane & 3) * 2;
#pragma unroll
    for (int mi = 0; mi < 2; mi++)
#pragma unroll
        for (int half = 0; half < 2; half++) {
            int m = m0 + wm0 + mi * 16 + lr + half * 8;
#pragma unroll
            for (int ni = 0; ni < 8; ni++) {
                int n = n0 + wn0 + ni * 8 + lc;
                float2 v;
                v.x = acc[mi][ni][half * 2 + 0];
                v.y = acc[mi][ni][half * 2 + 1];
                *(float2*)(Cf + (size_t)m * DMODEL + n) = v;
            }
        }
}

// ---------------- HMMA flash attention: 256 thr, Q-tile 128 ----------------
// grid (S/128, B*H), 8 warps, warp w owns q rows w*16..w*16+15
#define ASTR 72
#define ABUF (64*ASTR)     // elements per buffer (4608)
#define NBIAS 2176
__global__ __launch_bounds__(256) void attn_hmma(const int* __restrict__ mask) {
    extern __shared__ char sma[];
    __nv_bfloat16* stage = (__nv_bfloat16*)sma;      // 2 stages x {Kh,Kl,Vh,Vl}
    float* sBias = (float*)(stage + 2 * 4 * ABUF);   // 2176
    float* sMask = sBias + NBIAS;                    // 2048

    const int t = threadIdx.x, warp = t >> 5, lane = t & 31;
    const int q0 = blockIdx.x * 128, bh = blockIdx.y;
    const int b = bh >> 4, h = bh & 15;

    // sBias[j] = bias[h][ (kb+cl) - (q0+rl) ] where j = kb+cl-rl+127, rl in [0,128)
    for (int i = t; i < 2175; i += 256)
        sBias[i] = g_bias[h * NPOS + i + 1920 - q0];
    for (int i = t; i < 2048; i += 256)
        sMask[i] = mask[b * S_LEN + i] ? 0.f : -1e30f;

    const uint32_t uS = smem_u32(stage);
    const int lrow = lane & 15, lkh = lane >> 4;
    const int lr = lane >> 2, lc2 = (lane & 3) * 2;

    const __nv_bfloat16* Kh0 = g_kh + (size_t)bh * S_LEN * DKV;
    const __nv_bfloat16* Kl0 = g_kl + (size_t)bh * S_LEN * DKV;
    const __nv_bfloat16* Vh0 = g_vth + (size_t)bh * DKV * S_LEN;
    const __nv_bfloat16* Vl0 = g_vtl + (size_t)bh * DKV * S_LEN;

    // stage Q (128 rows) through the 4 stage-0 buffers, grab fragments, release
    {
        const __nv_bfloat16* Qh = g_qh + ((size_t)bh * S_LEN + q0) * DKV;
        const __nv_bfloat16* Ql = g_ql + ((size_t)bh * S_LEN + q0) * DKV;
        for (int i = t; i < 1024; i += 256) {
            int row = i >> 3, cv = i & 7;
            int slot = (row < 64) ? 0 : 2;
            int r = row & 63;
            *(uint4*)(stage + slot * ABUF + r * ASTR + cv * 8) =
                *(const uint4*)(Qh + row * 64 + cv * 8);
            *(uint4*)(stage + (slot + 1) * ABUF + r * ASTR + cv * 8) =
                *(const uint4*)(Ql + row * 64 + cv * 8);
        }
    }
    __syncthreads();
    uint32_t qh[4][4], ql[4][4];
    {
        uint32_t qbh = uS + ((warp >= 4) ? 2 * ABUF * 2 : 0);
        uint32_t qbl = qbh + ABUF * 2;
        int qr = (warp * 16) & 63;
#pragma unroll
        for (int ks = 0; ks < 4; ks++) {
            uint32_t ad = 2u * (uint32_t)((qr + lrow) * ASTR + ks * 16 + lkh * 8);
            ldsm_x4(qh[ks], qbh + ad);
            ldsm_x4(ql[ks], qbl + ad);
        }
    }
    __syncthreads();

    auto issueKV = [&](int kt, int s) {
        int kb = kt * 64;
        uint32_t sb = uS + (uint32_t)s * (4 * ABUF * 2);
#pragma unroll
        for (int rep = 0; rep < 2; rep++) {
            int i = t + rep * 256;             // 0..511
            int row = i >> 3, cv = i & 7;
            uint32_t so = sb + (uint32_t)(row * ASTR + cv * 8) * 2;
            cp16(so,                Kh0 + (size_t)(kb + row) * 64 + cv * 8);
            cp16(so + ABUF * 2,     Kl0 + (size_t)(kb + row) * 64 + cv * 8);
            cp16(so + 2 * ABUF * 2, Vh0 + (size_t)row * S_LEN + kb + cv * 8);
            cp16(so + 3 * ABUF * 2, Vl0 + (size_t)row * S_LEN + kb + cv * 8);
        }
        cp_commit();
    };

    float m_[2] = {-INFINITY, -INFINITY}, l_[2] = {0.f, 0.f};
    float o[8][4];
#pragma unroll
    for (int ni = 0; ni < 8; ni++)
#pragma unroll
        for (int j = 0; j < 4; j++) o[ni][j] = 0.f;

    issueKV(0, 0);
    for (int kt = 0; kt < S_LEN / 64; kt++) {
        int kb = kt * 64;
        if (kt < 31) { issueKV(kt + 1, (kt + 1) & 1); cp_wait1(); }
        else cp_wait0();
        __syncthreads();

        uint32_t sb = uS + (uint32_t)(kt & 1) * (4 * ABUF * 2);
        uint32_t uKh = sb, uKl = sb + ABUF * 2;
        uint32_t uVh = sb + 2 * ABUF * 2, uVl = sb + 3 * ABUF * 2;

        // S = Q K^T (bf16x3)
        float sc[8][4];
#pragma unroll
        for (int ni = 0; ni < 8; ni++)
#pragma unroll
            for (int j = 0; j < 4; j++) sc[ni][j] = 0.f;
#pragma unroll
        for (int ks = 0; ks < 4; ks++) {
            uint32_t kh_[4][4], kl_[4][4];
#pragma unroll
            for (int nt = 0; nt < 4; nt++) {
                uint32_t ad = 2u * (uint32_t)((nt * 16 + lrow) * ASTR + ks * 16 + lkh * 8);
                ldsm_x4(kh_[nt], uKh + ad);
                ldsm_x4(kl_[nt], uKl + ad);
            }
#pragma unroll
            for (int nt = 0; nt < 4; nt++) {
                uint32_t b0h[2] = {kh_[nt][0], kh_[nt][2]}, b1h[2] = {kh_[nt][1], kh_[nt][3]};
                uint32_t b0l[2] = {kl_[nt][0], kl_[nt][2]}, b1l[2] = {kl_[nt][1], kl_[nt][3]};
                mma_bf16(sc[nt * 2 + 0], qh[ks], b0h);
                mma_bf16(sc[nt * 2 + 1], qh[ks], b1h);
                mma_bf16(sc[nt * 2 + 0], qh[ks], b0l);
                mma_bf16(sc[nt * 2 + 1], qh[ks], b1l);
                mma_bf16(sc[nt * 2 + 0], ql[ks], b0h);
                mma_bf16(sc[nt * 2 + 1], ql[ks], b1h);
            }
        }

        // bias + mask + online softmax
#pragma unroll
        for (int half = 0; half < 2; half++) {
            int rl = warp * 16 + lr + half * 8;
            float tm = -INFINITY;
#pragma unroll
            for (int ni = 0; ni < 8; ni++) {
#pragma unroll
                for (int jc = 0; jc < 2; jc++) {
                    int cl = ni * 8 + lc2 + jc;
                    float v = sc[ni][half * 2 + jc]
                            + sBias[kb + cl - rl + 127] + sMask[kb + cl];
                    sc[ni][half * 2 + jc] = v;
                    tm = fmaxf(tm, v);
                }
            }
            tm = fmaxf(tm, __shfl_xor_sync(0xffffffffu, tm, 1));
            tm = fmaxf(tm, __shfl_xor_sync(0xffffffffu, tm, 2));
            float mnew = fmaxf(m_[half], tm);
            float alpha = __expf(m_[half] - mnew);
            float rs = 0.f;
#pragma unroll
            for (int ni = 0; ni < 8; ni++) {
#pragma unroll
                for (int jc = 0; jc < 2; jc++) {
                    float p = __expf(sc[ni][half * 2 + jc] - mnew);
                    sc[ni][half * 2 + jc] = p;
                    rs += p;
                }
            }
            rs += __shfl_xor_sync(0xffffffffu, rs, 1);
            rs += __shfl_xor_sync(0xffffffffu, rs, 2);
            l_[half] = l_[half] * alpha + rs;
            m_[half] = mnew;
#pragma unroll
            for (int ni = 0; ni < 8; ni++) {
                o[ni][half * 2 + 0] *= alpha;
                o[ni][half * 2 + 1] *= alpha;
            }
        }

        // O += P V  (P fragments built in-register; bf16x3)
#pragma unroll
        for (int ks = 0; ks < 4; ks++) {
            uint32_t ph[4], pl[4];
#pragma unroll
            for (int q = 0; q < 4; q++) {
                int ni = ks * 2 + (q >> 1);
                int ci = (q & 1) * 2;
                __nv_bfloat162 hp, lp;
                split2(sc[ni][ci], sc[ni][ci + 1], hp, lp);
                ph[q] = reinterpret_cast<uint32_t&>(hp);
                pl[q] = reinterpret_cast<uint32_t&>(lp);
            }
            uint32_t vh_[4][4], vl_[4][4];
#pragma unroll
            for (int nt = 0; nt < 4; nt++) {
                uint32_t ad = 2u * (uint32_t)((nt * 16 + lrow) * ASTR + ks * 16 + lkh * 8);
                ldsm_x4(vh_[nt], uVh + ad);
                ldsm_x4(vl_[nt], uVl + ad);
            }
#pragma unroll
            for (int nt = 0; nt < 4; nt++) {
                uint32_t b0h[2] = {vh_[nt][0], vh_[nt][2]}, b1h[2] = {vh_[nt][1], vh_[nt][3]};
                uint32_t b0l[2] = {vl_[nt][0], vl_[nt][2]}, b1l[2] = {vl_[nt][1], vl_[nt][3]};
                mma_bf16(o[nt * 2 + 0], ph, b0h);
                mma_bf16(o[nt * 2 + 1], ph, b1h);
                mma_bf16(o[nt * 2 + 0], ph, b0l);
                mma_bf16(o[nt * 2 + 1], ph, b1l);
                mma_bf16(o[nt * 2 + 0], pl, b0h);
                mma_bf16(o[nt * 2 + 1], pl, b1h);
            }
        }
        __syncthreads();
    }

    // epilogue: write bf16 hi/lo attn output [B,S,H*Dk]
#pragma unroll
    for (int half = 0; half < 2; half++) {
        int srow = q0 + warp * 16 + lr + half * 8;
        float inv = 1.f / l_[half];
        size_t base = ((size_t)b * S_LEN + srow) * DMODEL + h * 64;
#pragma unroll
        for (int ni = 0; ni < 8; ni++) {
            float f0 = o[ni][half * 2 + 0] * inv;
            float f1 = o[ni][half * 2 + 1] * inv;
            __nv_bfloat162 hp, lp;
            split2(f0, f1, hp, lp);
            *(__nv_bfloat162*)(g_aoh + base + ni * 8 + lc2) = hp;
            *(__nv_bfloat162*)(g_aol + base + ni * 8 + lc2) = lp;
        }
    }
}

// ---------------- launch ----------------
extern "C" void kernel_launch(void* const* d_in, const int* in_sizes, int n_in,
                              void* d_out, int out_size) {
    const float* hidden   = (const float*)d_in[0];
    const int*   mask     = (const int*)  d_in[1];
    const float* Wq       = (const float*)d_in[2];
    const float* Wk       = (const float*)d_in[3];
    const float* Wv       = (const float*)d_in[4];
    const float* Wo       = (const float*)d_in[5];
    const float* rel_bias = (const float*)d_in[6];
    float* out = (float*)d_out;

    __nv_bfloat16 *pxh, *pxl, *pwh, *pwl, *pqh, *pql, *pkh, *pkl,
                  *pvth, *pvtl, *paoh, *paol;
    cudaGetSymbolAddress((void**)&pxh,  g_xh);
    cudaGetSymbolAddress((void**)&pxl,  g_xl);
    cudaGetSymbolAddress((void**)&pwh,  g_wh);
    cudaGetSymbolAddress((void**)&pwl,  g_wl);
    cudaGetSymbolAddress((void**)&pqh,  g_qh);
    cudaGetSymbolAddress((void**)&pql,  g_ql);
    cudaGetSymbolAddress((void**)&pkh,  g_kh);
    cudaGetSymbolAddress((void**)&pkl,  g_kl);
    cudaGetSymbolAddress((void**)&pvth, g_vth);
    cudaGetSymbolAddress((void**)&pvtl, g_vtl);
    cudaGetSymbolAddress((void**)&paoh, g_aoh);
    cudaGetSymbolAddress((void**)&paol, g_aol);

    // 1) bias table
    bias_table_kernel<<<(HEADS * NPOS + 255) / 256, 256>>>(rel_bias);

    // 2) split hidden; transpose+split weights
    int nX = MTOT * DMODEL;
    split_hl_kernel<<<nX / 4 / 256, 256>>>(hidden, pxh, pxl, nX);
    dim3 tg(32, 32), tb(32, 8);
    const size_t WSZ = (size_t)DMODEL * DMODEL;
    transpose_split_kernel<<<tg, tb>>>(Wq, pwh + 0*WSZ, pwl + 0*WSZ);
    transpose_split_kernel<<<tg, tb>>>(Wk, pwh + 1*WSZ, pwl + 1*WSZ);
    transpose_split_kernel<<<tg, tb>>>(Wv, pwh + 2*WSZ, pwl + 2*WSZ);
    transpose_split_kernel<<<tg, tb>>>(Wo, pwh + 3*WSZ, pwl + 3*WSZ);

    // 3) merged QKV projections (bf16x3, BK=64, 2-stage cp.async)
    int gsmem = 2 * 4 * GBUF * (int)sizeof(__nv_bfloat16);   // 147456
    cudaFuncSetAttribute(hmma_gemm_qkv, cudaFuncAttributeMaxDynamicSharedMemorySize, gsmem);
    cudaFuncSetAttribute(hmma_gemm_out, cudaFuncAttributeMaxDynamicSharedMemorySize, gsmem);
    dim3 gq(DMODEL / 128, MTOT / 128, 3);  // (8, 32, 3)
    hmma_gemm_qkv<<<gq, 256, gsmem>>>(pxh, pxl, pwh, pwl,
                                      pqh, pql, pkh, pkl, pvth, pvtl);

    // 4) HMMA flash attention (256 thr, Q-tile 128)
    int asmem = 2 * 4 * ABUF * (int)sizeof(__nv_bfloat16)
              + (NBIAS + 2048) * (int)sizeof(float);         // 90624
    cudaFuncSetAttribute(attn_hmma, cudaFuncAttributeMaxDynamicSharedMemorySize, asmem);
    attn_hmma<<<dim3(S_LEN / 128, BATCH * HEADS), 256, asmem>>>(mask);

    // 5) output projection -> fp32 d_out
    dim3 gg(DMODEL / 128, MTOT / 128);     // (8, 32)
    hmma_gemm_out<<<gg, 256, gsmem>>>(paoh, paol, pwh + 3*WSZ, pwl + 3*WSZ, out);
}

// round 7
// speedup vs baseline: 3.2073x; 1.2702x over previous
#include <cuda_runtime.h>
#include <cuda_bf16.h>
#include <cuda_fp16.h>
#include <math.h>
#include <stdint.h>

#define S_LEN 2048
#define BATCH 2
#define HEADS 16
#define DKV 64
#define DMODEL 1024
#define NPOS (2*S_LEN-1)   // 4095
#define MTOT (BATCH*S_LEN) // 4096

// ---------------- device scratch (no allocations allowed) ----------------
__device__ float g_bias[HEADS*NPOS];             // bias[h][delta+2047]

__device__ __nv_bfloat16 g_xh[MTOT*DMODEL];      // hidden hi (bf16)
__device__ __nv_bfloat16 g_xl[MTOT*DMODEL];      // hidden lo
__device__ __nv_bfloat16 g_wh[4*DMODEL*DMODEL];  // Wq,Wk,Wv,Wo transposed [N,K] hi
__device__ __nv_bfloat16 g_wl[4*DMODEL*DMODEL];  // lo
__device__ __half g_q16h[BATCH*HEADS*S_LEN*DKV]; // q fp16 hi [B,H,S,Dk], scaled 1/8
__device__ __half g_q16l[BATCH*HEADS*S_LEN*DKV]; // q fp16 lo
__device__ __half g_k16 [BATCH*HEADS*S_LEN*DKV]; // k single fp16 [B,H,S,Dk]
__device__ __half g_vt16h[BATCH*HEADS*DKV*S_LEN];// V^T fp16 hi [B,H,Dk,S]
__device__ __half g_vt16l[BATCH*HEADS*DKV*S_LEN];// V^T fp16 lo
__device__ __nv_bfloat16 g_aoh[MTOT*DMODEL];     // attn out hi [B,S,H*Dk] (bf16)
__device__ __nv_bfloat16 g_aol[MTOT*DMODEL];     // attn out lo

// ---------------- helpers ----------------
__device__ __forceinline__ uint32_t smem_u32(const void* p) {
    uint32_t a;
    asm("{ .reg .u64 t; cvta.to.shared.u64 t, %1; cvt.u32.u64 %0, t; }"
        : "=r"(a) : "l"(p));
    return a;
}
__device__ __forceinline__ void ldsm_x4(uint32_t* r, uint32_t addr) {
    asm volatile("ldmatrix.sync.aligned.m8n8.x4.shared.b16 {%0,%1,%2,%3}, [%4];"
                 : "=r"(r[0]), "=r"(r[1]), "=r"(r[2]), "=r"(r[3]) : "r"(addr));
}
__device__ __forceinline__ void mma_bf16(float* d, const uint32_t* a,
                                         const uint32_t* b) {
    asm volatile(
        "mma.sync.aligned.m16n8k16.row.col.f32.bf16.bf16.f32 "
        "{%0,%1,%2,%3}, {%4,%5,%6,%7}, {%8,%9}, {%0,%1,%2,%3};"
        : "+f"(d[0]), "+f"(d[1]), "+f"(d[2]), "+f"(d[3])
        : "r"(a[0]), "r"(a[1]), "r"(a[2]), "r"(a[3]), "r"(b[0]), "r"(b[1]));
}
__device__ __forceinline__ void mma_f16(float* d, const uint32_t* a,
                                        const uint32_t* b) {
    asm volatile(
        "mma.sync.aligned.m16n8k16.row.col.f32.f16.f16.f32 "
        "{%0,%1,%2,%3}, {%4,%5,%6,%7}, {%8,%9}, {%0,%1,%2,%3};"
        : "+f"(d[0]), "+f"(d[1]), "+f"(d[2]), "+f"(d[3])
        : "r"(a[0]), "r"(a[1]), "r"(a[2]), "r"(a[3]), "r"(b[0]), "r"(b[1]));
}
__device__ __forceinline__ void split2(float f0, float f1,
                                       __nv_bfloat162& hp, __nv_bfloat162& lp) {
    hp = __floats2bfloat162_rn(f0, f1);
    float2 hf = __bfloat1622float2(hp);
    lp = __floats2bfloat162_rn(f0 - hf.x, f1 - hf.y);
}
__device__ __forceinline__ void cp16(uint32_t s, const void* g) {
    asm volatile("cp.async.cg.shared.global [%0], [%1], 16;" :: "r"(s), "l"(g));
}
__device__ __forceinline__ void cp_commit() {
    asm volatile("cp.async.commit_group;" ::: "memory");
}
__device__ __forceinline__ void cp_wait1() {
    asm volatile("cp.async.wait_group 1;" ::: "memory");
}
__device__ __forceinline__ void cp_wait0() {
    asm volatile("cp.async.wait_group 0;" ::: "memory");
}

// ---------------- relative position bias table ----------------
__global__ void bias_table_kernel(const float* __restrict__ rel_bias) {
    int idx = blockIdx.x * blockDim.x + threadIdx.x;
    if (idx >= HEADS * NPOS) return;
    int h = idx / NPOS;
    int delta = (idx % NPOS) - (S_LEN - 1);
    int ad = delta < 0 ? -delta : delta;
    int bucket = (delta > 0) ? 16 : 0;
    if (ad < 8) {
        bucket += ad;
    } else {
        int lg = 31 - __clz(ad * ad);      // floor(2*log2(ad))
        int bl = lg + 2;
        bucket += (bl > 15) ? 15 : bl;
    }
    g_bias[idx] = rel_bias[bucket * HEADS + h];
}

// ---------------- fp32 -> bf16 hi/lo split ----------------
__global__ void split_hl_kernel(const float* __restrict__ x,
                                __nv_bfloat16* __restrict__ hi,
                                __nv_bfloat16* __restrict__ lo, int n) {
    int i = (blockIdx.x * blockDim.x + threadIdx.x) * 4;
    if (i >= n) return;
    float4 v = *(const float4*)(x + i);
    __nv_bfloat162 h0, l0, h1, l1;
    split2(v.x, v.y, h0, l0);
    split2(v.z, v.w, h1, l1);
    __nv_bfloat162* hp = (__nv_bfloat162*)(hi + i);
    __nv_bfloat162* lp = (__nv_bfloat162*)(lo + i);
    hp[0] = h0; hp[1] = h1;
    lp[0] = l0; lp[1] = l1;
}

// ---------------- transpose + split, two weights per launch ----------------
__global__ void transpose_split2_kernel(const float* __restrict__ W0,
                                        const float* __restrict__ W1,
                                        __nv_bfloat16* __restrict__ Th,
                                        __nv_bfloat16* __restrict__ Tl) {
    __shared__ float tile[32][33];
    const float* W = blockIdx.z ? W1 : W0;
    size_t off = (size_t)blockIdx.z * DMODEL * DMODEL;
    int n0 = blockIdx.x * 32, k0 = blockIdx.y * 32;
    int tx = threadIdx.x, ty = threadIdx.y;
    for (int r = ty; r < 32; r += 8)
        tile[r][tx] = W[(size_t)(k0 + r) * DMODEL + n0 + tx];
    __syncthreads();
    for (int r = ty; r < 32; r += 8) {
        float v = tile[tx][r];     // = W[k0+tx][n0+r]
        __nv_bfloat16 h = __float2bfloat16(v);
        __nv_bfloat16 l = __float2bfloat16(v - __bfloat162float(h));
        size_t o = off + (size_t)(n0 + r) * DMODEL + k0 + tx;
        Th[o] = h; Tl[o] = l;
    }
}

// ---------------- GEMM core: bf16x3, BK=64, 2-stage cp.async ----------------
#define SSTR 72            // smem row stride in bf16 (64 + 8 pad)
#define GBUF (128*SSTR)    // elements per buffer (9216)
__device__ __forceinline__ void gemm_tile(
    const __nv_bfloat16* __restrict__ Ah, const __nv_bfloat16* __restrict__ Al,
    const __nv_bfloat16* __restrict__ Bh, const __nv_bfloat16* __restrict__ Bl,
    int m0, int n0, __nv_bfloat16* sm16, int t, float acc[2][8][4])
{
    const int wid = t >> 5, lane = t & 31;
    const int wm0 = (wid & 3) * 32, wn0 = (wid >> 2) * 64;
    const uint32_t ub = smem_u32(sm16);
    const int lrow = lane & 15, lkh = lane >> 4;

    auto issue = [&](int c, int s) {
        int k0 = c * 64;
        uint32_t sb = ub + (uint32_t)s * (4 * GBUF * 2);
#pragma unroll
        for (int rep = 0; rep < 4; rep++) {
            int i = t + rep * 256;           // 0..1023
            int row = i >> 3, cv = i & 7;
            uint32_t so = sb + (uint32_t)(row * SSTR + cv * 8) * 2;
            size_t ga = (size_t)(m0 + row) * DMODEL + k0 + cv * 8;
            size_t gb = (size_t)(n0 + row) * DMODEL + k0 + cv * 8;
            cp16(so,                Ah + ga);
            cp16(so + GBUF * 2,     Al + ga);
            cp16(so + 2 * GBUF * 2, Bh + gb);
            cp16(so + 3 * GBUF * 2, Bl + gb);
        }
        cp_commit();
    };

    issue(0, 0);
    for (int c = 0; c < 16; c++) {
        if (c < 15) { issue(c + 1, (c + 1) & 1); cp_wait1(); }
        else cp_wait0();
        __syncthreads();

        uint32_t sb = ub + (uint32_t)(c & 1) * (4 * GBUF * 2);
        uint32_t uAh = sb,                uAl = sb + GBUF * 2;
        uint32_t uBh = sb + 2 * GBUF * 2, uBl = sb + 3 * GBUF * 2;
#pragma unroll
        for (int ks = 0; ks < 4; ks++) {
            int kk = ks * 16;
            uint32_t ah[2][4], al[2][4], bh[4][4], bl[4][4];
#pragma unroll
            for (int mi = 0; mi < 2; mi++) {
                uint32_t ad = 2u * (uint32_t)((wm0 + mi * 16 + lrow) * SSTR + kk + lkh * 8);
                ldsm_x4(ah[mi], uAh + ad);
                ldsm_x4(al[mi], uAl + ad);
            }
#pragma unroll
            for (int nt = 0; nt < 4; nt++) {
                uint32_t ad = 2u * (uint32_t)((wn0 + nt * 16 + lrow) * SSTR + kk + lkh * 8);
                ldsm_x4(bh[nt], uBh + ad);
                ldsm_x4(bl[nt], uBl + ad);
            }
#pragma unroll
            for (int mi = 0; mi < 2; mi++)
#pragma unroll
                for (int nt = 0; nt < 4; nt++) {
                    uint32_t b0h[2] = {bh[nt][0], bh[nt][2]}, b1h[2] = {bh[nt][1], bh[nt][3]};
                    uint32_t b0l[2] = {bl[nt][0], bl[nt][2]}, b1l[2] = {bl[nt][1], bl[nt][3]};
                    mma_bf16(acc[mi][nt * 2 + 0], ah[mi], b0h);
                    mma_bf16(acc[mi][nt * 2 + 1], ah[mi], b1h);
                    mma_bf16(acc[mi][nt * 2 + 0], ah[mi], b0l);
                    mma_bf16(acc[mi][nt * 2 + 1], ah[mi], b1l);
                    mma_bf16(acc[mi][nt * 2 + 0], al[mi], b0h);
                    mma_bf16(acc[mi][nt * 2 + 1], al[mi], b1h);
                }
        }
        __syncthreads();
    }
}

// ---------------- merged QKV projection (grid.z selects weight slab) ----------------
// z=0: Q -> fp16 hi/lo [B,H,S,Dk], scaled 1/8
// z=1: K -> fp16 single [B,H,S,Dk]
// z=2: V -> fp16 hi/lo transposed [B,H,Dk,S]
__global__ __launch_bounds__(256) void hmma_gemm_qkv(
    const __nv_bfloat16* __restrict__ Ah, const __nv_bfloat16* __restrict__ Al,
    const __nv_bfloat16* __restrict__ Wh, const __nv_bfloat16* __restrict__ Wl)
{
    extern __shared__ __nv_bfloat16 sm16[];
    const int t = threadIdx.x, wid = t >> 5, lane = t & 31;
    const int m0 = blockIdx.y * 128, n0 = blockIdx.x * 128;
    const int z = blockIdx.z;
    const size_t WSZ = (size_t)DMODEL * DMODEL;

    float acc[2][8][4];
#pragma unroll
    for (int mi = 0; mi < 2; mi++)
#pragma unroll
        for (int ni = 0; ni < 8; ni++)
#pragma unroll
            for (int j = 0; j < 4; j++) acc[mi][ni][j] = 0.f;

    gemm_tile(Ah, Al, Wh + z * WSZ, Wl + z * WSZ, m0, n0, sm16, t, acc);

    const float scale = (z == 0) ? 0.125f : 1.0f;
    const int wm0 = (wid & 3) * 32, wn0 = (wid >> 2) * 64;
    const int lr = lane >> 2, lc = (lane & 3) * 2;
#pragma unroll
    for (int mi = 0; mi < 2; mi++) {
#pragma unroll
        for (int half = 0; half < 2; half++) {
            int m = m0 + wm0 + mi * 16 + lr + half * 8;
#pragma unroll
            for (int ni = 0; ni < 8; ni++) {
                int n = n0 + wn0 + ni * 8 + lc;
                float f0 = acc[mi][ni][half * 2 + 0] * scale;
                float f1 = acc[mi][ni][half * 2 + 1] * scale;
                int b = m >> 11, s = m & 2047, h = n >> 6, d = n & 63;
                if (z == 0) {
                    size_t o = (((size_t)(b * HEADS + h)) * S_LEN + s) * DKV + d;
                    __half2 hp = __floats2half2_rn(f0, f1);
                    float2 hf = __half22float2(hp);
                    __half2 lp = __floats2half2_rn(f0 - hf.x, f1 - hf.y);
                    *(__half2*)(g_q16h + o) = hp;
                    *(__half2*)(g_q16l + o) = lp;
                } else if (z == 1) {
                    size_t o = (((size_t)(b * HEADS + h)) * S_LEN + s) * DKV + d;
                    *(__half2*)(g_k16 + o) = __floats2half2_rn(f0, f1);
                } else {
                    size_t o = (((size_t)(b * HEADS + h)) * DKV + d) * S_LEN + s;
                    __half h0 = __float2half_rn(f0), h1 = __float2half_rn(f1);
                    __half l0 = __float2half_rn(f0 - __half2float(h0));
                    __half l1 = __float2half_rn(f1 - __half2float(h1));
                    g_vt16h[o] = h0; g_vt16h[o + S_LEN] = h1;
                    g_vt16l[o] = l0; g_vt16l[o + S_LEN] = l1;
                }
            }
        }
    }
}

// ---------------- output projection -> fp32 ----------------
__global__ __launch_bounds__(256) void hmma_gemm_out(
    const __nv_bfloat16* __restrict__ Ah, const __nv_bfloat16* __restrict__ Al,
    const __nv_bfloat16* __restrict__ Bh, const __nv_bfloat16* __restrict__ Bl,
    float* __restrict__ Cf)
{
    extern __shared__ __nv_bfloat16 sm16[];
    const int t = threadIdx.x, wid = t >> 5, lane = t & 31;
    const int m0 = blockIdx.y * 128, n0 = blockIdx.x * 128;

    float acc[2][8][4];
#pragma unroll
    for (int mi = 0; mi < 2; mi++)
#pragma unroll
        for (int ni = 0; ni < 8; ni++)
#pragma unroll
            for (int j = 0; j < 4; j++) acc[mi][ni][j] = 0.f;

    gemm_tile(Ah, Al, Bh, Bl, m0, n0, sm16, t, acc);

    const int wm0 = (wid & 3) * 32, wn0 = (wid >> 2) * 64;
    const int lr = lane >> 2, lc = (lane & 3) * 2;
#pragma unroll
    for (int mi = 0; mi < 2; mi++)
#pragma unroll
        for (int half = 0; half < 2; half++) {
            int m = m0 + wm0 + mi * 16 + lr + half * 8;
#pragma unroll
            for (int ni = 0; ni < 8; ni++) {
                int n = n0 + wn0 + ni * 8 + lc;
                float2 v;
                v.x = acc[mi][ni][half * 2 + 0];
                v.y = acc[mi][ni][half * 2 + 1];
                *(float2*)(Cf + (size_t)m * DMODEL + n) = v;
            }
        }
}

// ---------------- fp16 flash attention: 256 thr, Q-tile 128, 2-pass ----------------
// grid (S/128, B*H). Buffers per stage: {K, Vh, Vl}.
#define ASTR 72
#define ABUF (64*ASTR)     // elements per buffer (4608)
#define NBIAS 2176
__global__ __launch_bounds__(256) void attn_hmma(const int* __restrict__ mask) {
    extern __shared__ char sma[];
    __half* stage = (__half*)sma;                    // 2 stages x {K,Vh,Vl}
    float* sBias = (float*)(stage + 2 * 3 * ABUF);   // 2176
    float* sMask = sBias + NBIAS;                    // 2048

    const int t = threadIdx.x, warp = t >> 5, lane = t & 31;
    const int q0 = blockIdx.x * 128, bh = blockIdx.y;
    const int b = bh >> 4, h = bh & 15;

    for (int i = t; i < 2175; i += 256)
        sBias[i] = g_bias[h * NPOS + i + 1920 - q0];
    for (int i = t; i < 2048; i += 256)
        sMask[i] = mask[b * S_LEN + i] ? 0.f : -1e30f;

    const uint32_t uS = smem_u32(stage);
    const int lrow = lane & 15, lkh = lane >> 4;
    const int lr = lane >> 2, lc2 = (lane & 3) * 2;

    const __half* K0  = g_k16  + (size_t)bh * S_LEN * DKV;
    const __half* Vh0 = g_vt16h + (size_t)bh * DKV * S_LEN;
    const __half* Vl0 = g_vt16l + (size_t)bh * DKV * S_LEN;

    // stage Q (128 rows hi+lo) through 4 of the 6 buffers, grab fragments
    {
        const __half* Qh = g_q16h + ((size_t)bh * S_LEN + q0) * DKV;
        const __half* Ql = g_q16l + ((size_t)bh * S_LEN + q0) * DKV;
        for (int i = t; i < 1024; i += 256) {
            int row = i >> 3, cv = i & 7;
            int hb = (row < 64) ? 0 : 1, r = row & 63;
            *(uint4*)(stage + hb * ABUF + r * ASTR + cv * 8) =
                *(const uint4*)(Qh + row * 64 + cv * 8);
            *(uint4*)(stage + (hb + 2) * ABUF + r * ASTR + cv * 8) =
                *(const uint4*)(Ql + row * 64 + cv * 8);
        }
    }
    __syncthreads();
    uint32_t qh[4][4], ql[4][4];
    {
        uint32_t qbh = uS + ((warp >= 4) ? ABUF * 2 : 0);
        uint32_t qbl = qbh + 2 * ABUF * 2;
        int qr = (warp * 16) & 63;
#pragma unroll
        for (int ks = 0; ks < 4; ks++) {
            uint32_t ad = 2u * (uint32_t)((qr + lrow) * ASTR + ks * 16 + lkh * 8);
            ldsm_x4(qh[ks], qbh + ad);
            ldsm_x4(ql[ks], qbl + ad);
        }
    }
    __syncthreads();

    auto issueKV = [&](int kt, int s) {
        int kb = kt * 64;
        uint32_t sb = uS + (uint32_t)s * (3 * ABUF * 2);
#pragma unroll
        for (int rep = 0; rep < 2; rep++) {
            int i = t + rep * 256;             // 0..511
            int row = i >> 3, cv = i & 7;
            uint32_t so = sb + (uint32_t)(row * ASTR + cv * 8) * 2;
            cp16(so,                K0  + (size_t)(kb + row) * 64 + cv * 8);
            cp16(so + ABUF * 2,     Vh0 + (size_t)row * S_LEN + kb + cv * 8);
            cp16(so + 2 * ABUF * 2, Vl0 + (size_t)row * S_LEN + kb + cv * 8);
        }
        cp_commit();
    };

    float m_[2] = {-INFINITY, -INFINITY}, l_[2] = {0.f, 0.f};
    float o[8][4];
#pragma unroll
    for (int ni = 0; ni < 8; ni++)
#pragma unroll
        for (int j = 0; j < 4; j++) o[ni][j] = 0.f;

    issueKV(0, 0);
    for (int kt = 0; kt < S_LEN / 64; kt++) {
        int kb = kt * 64;
        if (kt < 31) { issueKV(kt + 1, (kt + 1) & 1); cp_wait1(); }
        else cp_wait0();
        __syncthreads();

        uint32_t sb = uS + (uint32_t)(kt & 1) * (3 * ABUF * 2);
        uint32_t uK = sb, uVh = sb + ABUF * 2, uVl = sb + 2 * ABUF * 2;

        // S = Q K^T (Q fp16 hi/lo, K single fp16: 2 passes)
        float sc[8][4];
#pragma unroll
        for (int ni = 0; ni < 8; ni++)
#pragma unroll
            for (int j = 0; j < 4; j++) sc[ni][j] = 0.f;
#pragma unroll
        for (int ks = 0; ks < 4; ks++) {
            uint32_t k_[4][4];
#pragma unroll
            for (int nt = 0; nt < 4; nt++) {
                uint32_t ad = 2u * (uint32_t)((nt * 16 + lrow) * ASTR + ks * 16 + lkh * 8);
                ldsm_x4(k_[nt], uK + ad);
            }
#pragma unroll
            for (int nt = 0; nt < 4; nt++) {
                uint32_t b0[2] = {k_[nt][0], k_[nt][2]}, b1[2] = {k_[nt][1], k_[nt][3]};
                mma_f16(sc[nt * 2 + 0], qh[ks], b0);
                mma_f16(sc[nt * 2 + 1], qh[ks], b1);
                mma_f16(sc[nt * 2 + 0], ql[ks], b0);
                mma_f16(sc[nt * 2 + 1], ql[ks], b1);
            }
        }

        // bias + mask + online softmax
#pragma unroll
        for (int half = 0; half < 2; half++) {
            int rl = warp * 16 + lr + half * 8;
            float tm = -INFINITY;
#pragma unroll
            for (int ni = 0; ni < 8; ni++) {
#pragma unroll
                for (int jc = 0; jc < 2; jc++) {
                    int cl = ni * 8 + lc2 + jc;
                    float v = sc[ni][half * 2 + jc]
                            + sBias[kb + cl - rl + 127] + sMask[kb + cl];
                    sc[ni][half * 2 + jc] = v;
                    tm = fmaxf(tm, v);
                }
            }
            tm = fmaxf(tm, __shfl_xor_sync(0xffffffffu, tm, 1));
            tm = fmaxf(tm, __shfl_xor_sync(0xffffffffu, tm, 2));
            float mnew = fmaxf(m_[half], tm);
            float alpha = __expf(m_[half] - mnew);
            float rs = 0.f;
#pragma unroll
            for (int ni = 0; ni < 8; ni++) {
#pragma unroll
                for (int jc = 0; jc < 2; jc++) {
                    float p = __expf(sc[ni][half * 2 + jc] - mnew);
                    sc[ni][half * 2 + jc] = p;
                    rs += p;
                }
            }
            rs += __shfl_xor_sync(0xffffffffu, rs, 1);
            rs += __shfl_xor_sync(0xffffffffu, rs, 2);
            l_[half] = l_[half] * alpha + rs;
            m_[half] = mnew;
#pragma unroll
            for (int ni = 0; ni < 8; ni++) {
                o[ni][half * 2 + 0] *= alpha;
                o[ni][half * 2 + 1] *= alpha;
            }
        }

        // O += P V  (P single fp16, V fp16 hi/lo: 2 passes)
#pragma unroll
        for (int ks = 0; ks < 4; ks++) {
            uint32_t ph[4];
#pragma unroll
            for (int q = 0; q < 4; q++) {
                int ni = ks * 2 + (q >> 1);
                int ci = (q & 1) * 2;
                __half2 hp = __floats2half2_rn(sc[ni][ci], sc[ni][ci + 1]);
                ph[q] = reinterpret_cast<uint32_t&>(hp);
            }
            uint32_t vh_[4][4], vl_[4][4];
#pragma unroll
            for (int nt = 0; nt < 4; nt++) {
                uint32_t ad = 2u * (uint32_t)((nt * 16 + lrow) * ASTR + ks * 16 + lkh * 8);
                ldsm_x4(vh_[nt], uVh + ad);
                ldsm_x4(vl_[nt], uVl + ad);
            }
#pragma unroll
            for (int nt = 0; nt < 4; nt++) {
                uint32_t b0h[2] = {vh_[nt][0], vh_[nt][2]}, b1h[2] = {vh_[nt][1], vh_[nt][3]};
                uint32_t b0l[2] = {vl_[nt][0], vl_[nt][2]}, b1l[2] = {vl_[nt][1], vl_[nt][3]};
                mma_f16(o[nt * 2 + 0], ph, b0h);
                mma_f16(o[nt * 2 + 1], ph, b1h);
                mma_f16(o[nt * 2 + 0], ph, b0l);
                mma_f16(o[nt * 2 + 1], ph, b1l);
            }
        }
        __syncthreads();
    }

    // epilogue: write bf16 hi/lo attn output [B,S,H*Dk]
#pragma unroll
    for (int half = 0; half < 2; half++) {
        int srow = q0 + warp * 16 + lr + half * 8;
        float inv = 1.f / l_[half];
        size_t base = ((size_t)b * S_LEN + srow) * DMODEL + h * 64;
#pragma unroll
        for (int ni = 0; ni < 8; ni++) {
            float f0 = o[ni][half * 2 + 0] * inv;
            float f1 = o[ni][half * 2 + 1] * inv;
            __nv_bfloat162 hp, lp;
            split2(f0, f1, hp, lp);
            *(__nv_bfloat162*)(g_aoh + base + ni * 8 + lc2) = hp;
            *(__nv_bfloat162*)(g_aol + base + ni * 8 + lc2) = lp;
        }
    }
}

// ---------------- launch ----------------
extern "C" void kernel_launch(void* const* d_in, const int* in_sizes, int n_in,
                              void* d_out, int out_size) {
    const float* hidden   = (const float*)d_in[0];
    const int*   mask     = (const int*)  d_in[1];
    const float* Wq       = (const float*)d_in[2];
    const float* Wk       = (const float*)d_in[3];
    const float* Wv       = (const float*)d_in[4];
    const float* Wo       = (const float*)d_in[5];
    const float* rel_bias = (const float*)d_in[6];
    float* out = (float*)d_out;

    __nv_bfloat16 *pxh, *pxl, *pwh, *pwl, *paoh, *paol;
    cudaGetSymbolAddress((void**)&pxh,  g_xh);
    cudaGetSymbolAddress((void**)&pxl,  g_xl);
    cudaGetSymbolAddress((void**)&pwh,  g_wh);
    cudaGetSymbolAddress((void**)&pwl,  g_wl);
    cudaGetSymbolAddress((void**)&paoh, g_aoh);
    cudaGetSymbolAddress((void**)&paol, g_aol);

    const size_t WSZ = (size_t)DMODEL * DMODEL;
    int nX = MTOT * DMODEL;

    // launches 1-4: prep (ncu -s 5 -c 1 then captures launch 6 = attn_hmma)
    bias_table_kernel<<<(HEADS * NPOS + 255) / 256, 256>>>(rel_bias);
    split_hl_kernel<<<nX / 4 / 256, 256>>>(hidden, pxh, pxl, nX);
    dim3 tg(32, 32, 2), tb(32, 8);
    transpose_split2_kernel<<<tg, tb>>>(Wq, Wk, pwh, pwl);
    transpose_split2_kernel<<<tg, tb>>>(Wv, Wo, pwh + 2*WSZ, pwl + 2*WSZ);

    // launch 5: merged QKV projections (bf16x3)
    int gsmem = 2 * 4 * GBUF * (int)sizeof(__nv_bfloat16);   // 147456
    cudaFuncSetAttribute(hmma_gemm_qkv, cudaFuncAttributeMaxDynamicSharedMemorySize, gsmem);
    cudaFuncSetAttribute(hmma_gemm_out, cudaFuncAttributeMaxDynamicSharedMemorySize, gsmem);
    dim3 gq(DMODEL / 128, MTOT / 128, 3);
    hmma_gemm_qkv<<<gq, 256, gsmem>>>(pxh, pxl, pwh, pwl);

    // launch 6: fp16 flash attention (2-pass QK / 2-pass PV)
    int asmem = 2 * 3 * ABUF * (int)sizeof(__half)
              + (NBIAS + 2048) * (int)sizeof(float);         // 72192
    cudaFuncSetAttribute(attn_hmma, cudaFuncAttributeMaxDynamicSharedMemorySize, asmem);
    attn_hmma<<<dim3(S_LEN / 128, BATCH * HEADS), 256, asmem>>>(mask);

    // launch 7: output projection -> fp32 d_out
    dim3 gg(DMODEL / 128, MTOT / 128);
    hmma_gemm_out<<<gg, 256, gsmem>>>(paoh, paol, pwh + 3*WSZ, pwl + 3*WSZ, out);
}